// round 1
// baseline (speedup 1.0000x reference)
#include <cuda_runtime.h>
#include <cstdint>

// Problem constants
#define B_DIM   64
#define C_DIM   512
#define T_DIM   256
#define Q_LAYERS 6
#define K_CODES 1024
#define M_TOT   (B_DIM * T_DIM)          // 16384 vectors
#define OUT_QOUT_ELEMS (B_DIM * C_DIM * T_DIM)   // 8388608
#define OUT_IDX_ELEMS  (B_DIM * T_DIM * Q_LAYERS) // 98304

// Scratch (no allocation allowed -> __device__ globals)
__device__ float  g_X[M_TOT * C_DIM];        // residual, (M, C) row-major, ~33.5 MB
__device__ int    g_idx[Q_LAYERS * M_TOT];   // argmin indices per layer
__device__ float  g_norm[K_CODES];           // per-layer code norms
__device__ int    g_hist[K_CODES];           // per-layer usage histogram
__device__ double g_commit[Q_LAYERS];        // commit-loss accumulators
__device__ float  g_perp[Q_LAYERS];          // per-layer perplexity

// ---------------------------------------------------------------------------
// 1) Transpose input x (B, C, T) -> g_X (B*T, C)
// ---------------------------------------------------------------------------
__global__ void transpose_in_kernel(const float* __restrict__ x)
{
    __shared__ float tile[32][33];
    const int b  = blockIdx.z;
    const int c0 = blockIdx.y * 32;
    const int t0 = blockIdx.x * 32;
    const int tx = threadIdx.x;      // 0..31
    const int ty = threadIdx.y;      // 0..7

    const float* xp = x + (size_t)b * C_DIM * T_DIM;
#pragma unroll
    for (int i = ty; i < 32; i += 8)               // i = c-local
        tile[i][tx] = xp[(size_t)(c0 + i) * T_DIM + t0 + tx];   // tx = t-local
    __syncthreads();
#pragma unroll
    for (int i = ty; i < 32; i += 8)               // i = t-local
        g_X[(size_t)(b * T_DIM + t0 + i) * C_DIM + c0 + tx] = tile[tx][i];
}

// ---------------------------------------------------------------------------
// 2) Per-layer: code norms + histogram/commit init
// ---------------------------------------------------------------------------
__global__ void norms_init_kernel(const float* __restrict__ cb, int q)
{
    __shared__ float red[128];
    const int k   = blockIdx.x;      // 0..1023
    const int tid = threadIdx.x;     // 0..127
    const float4 c = reinterpret_cast<const float4*>(cb + (size_t)k * C_DIM)[tid];
    red[tid] = c.x * c.x + c.y * c.y + c.z * c.z + c.w * c.w;
    __syncthreads();
    for (int off = 64; off > 0; off >>= 1) {
        if (tid < off) red[tid] += red[tid + off];
        __syncthreads();
    }
    if (tid == 0) {
        g_norm[k] = red[0];
        g_hist[k] = 0;
        if (k == 0) g_commit[q] = 0.0;
    }
}

// ---------------------------------------------------------------------------
// 3) Fused GEMM + argmin.
//    Block: 64 rows of X vs ALL 1024 codes (16 tiles of 64), C-loop in 16s.
//    256 threads, 4x4 micro-tile each. No cross-block reduction needed.
// ---------------------------------------------------------------------------
__global__ __launch_bounds__(256) void gemm_argmin_kernel(
    const float* __restrict__ cb, int q)
{
    __shared__ __align__(16) float As[16][64];
    __shared__ __align__(16) float Bs[16][64];

    const int tid  = threadIdx.x;
    const int tx   = tid & 15;       // column group
    const int ty   = tid >> 4;       // row group
    const int m0   = blockIdx.x * 64;
    const int lrow = tid >> 2;       // 0..63 (load row)
    const int lc   = (tid & 3) * 4;  // 0,4,8,12 (load col within 16-chunk)

    float bestv[4];
    int   besti[4];
#pragma unroll
    for (int i = 0; i < 4; ++i) { bestv[i] = 3.4e38f; besti[i] = 0; }

    const float* Arow = g_X + (size_t)(m0 + lrow) * C_DIM + lc;

    for (int nt = 0; nt < K_CODES / 64; ++nt) {
        const int n0 = nt * 64;
        const float* Brow = cb + (size_t)(n0 + lrow) * C_DIM + lc;

        float acc[4][4];
#pragma unroll
        for (int i = 0; i < 4; ++i)
#pragma unroll
            for (int j = 0; j < 4; ++j) acc[i][j] = 0.0f;

        for (int ck = 0; ck < C_DIM; ck += 16) {
            const float4 a4 = *reinterpret_cast<const float4*>(Arow + ck);
            const float4 b4 = *reinterpret_cast<const float4*>(Brow + ck);
            __syncthreads();   // previous tile fully consumed
            As[lc + 0][lrow] = a4.x; As[lc + 1][lrow] = a4.y;
            As[lc + 2][lrow] = a4.z; As[lc + 3][lrow] = a4.w;
            Bs[lc + 0][lrow] = b4.x; Bs[lc + 1][lrow] = b4.y;
            Bs[lc + 2][lrow] = b4.z; Bs[lc + 3][lrow] = b4.w;
            __syncthreads();
#pragma unroll
            for (int k = 0; k < 16; ++k) {
                const float4 ar = *reinterpret_cast<const float4*>(&As[k][ty * 4]);
                const float4 br = *reinterpret_cast<const float4*>(&Bs[k][tx * 4]);
                acc[0][0] += ar.x * br.x; acc[0][1] += ar.x * br.y;
                acc[0][2] += ar.x * br.z; acc[0][3] += ar.x * br.w;
                acc[1][0] += ar.y * br.x; acc[1][1] += ar.y * br.y;
                acc[1][2] += ar.y * br.z; acc[1][3] += ar.y * br.w;
                acc[2][0] += ar.z * br.x; acc[2][1] += ar.z * br.y;
                acc[2][2] += ar.z * br.z; acc[2][3] += ar.z * br.w;
                acc[3][0] += ar.w * br.x; acc[3][1] += ar.w * br.y;
                acc[3][2] += ar.w * br.z; acc[3][3] += ar.w * br.w;
            }
        }

#pragma unroll
        for (int i = 0; i < 4; ++i) {
#pragma unroll
            for (int j = 0; j < 4; ++j) {
                const int n = n0 + tx * 4 + j;
                const float s = g_norm[n] - 2.0f * acc[i][j];
                if (s < bestv[i]) { bestv[i] = s; besti[i] = n; }  // first-min tiebreak
            }
        }
    }

    // reduce argmin across the 16 tx lanes sharing each row (width-16 shuffles)
#pragma unroll
    for (int i = 0; i < 4; ++i) {
        float v  = bestv[i];
        int   ix = besti[i];
#pragma unroll
        for (int off = 8; off > 0; off >>= 1) {
            const float ov = __shfl_xor_sync(0xffffffffu, v, off, 16);
            const int   oi = __shfl_xor_sync(0xffffffffu, ix, off, 16);
            if (ov < v || (ov == v && oi < ix)) { v = ov; ix = oi; }
        }
        if (tx == 0) g_idx[q * M_TOT + m0 + ty * 4 + i] = ix;
    }
}

// ---------------------------------------------------------------------------
// 4) Residual update + commit accumulation + histogram
//    residual_new = residual - cb[idx];  commit_q += sum(residual_new^2)
// ---------------------------------------------------------------------------
__global__ void update_kernel(const float* __restrict__ cb, int q)
{
    __shared__ float red[128];
    const int m   = blockIdx.x;      // 0..16383
    const int tid = threadIdx.x;     // 0..127
    const int idx = g_idx[q * M_TOT + m];

    const float4 c = reinterpret_cast<const float4*>(cb + (size_t)idx * C_DIM)[tid];
    float4* xp = reinterpret_cast<float4*>(g_X + (size_t)m * C_DIM);
    float4 r = xp[tid];
    r.x -= c.x; r.y -= c.y; r.z -= c.z; r.w -= c.w;
    xp[tid] = r;

    red[tid] = r.x * r.x + r.y * r.y + r.z * r.z + r.w * r.w;
    __syncthreads();
    for (int off = 64; off > 0; off >>= 1) {
        if (tid < off) red[tid] += red[tid + off];
        __syncthreads();
    }
    if (tid == 0) {
        atomicAdd(&g_commit[q], (double)red[0]);
        atomicAdd(&g_hist[idx], 1);
    }
}

// ---------------------------------------------------------------------------
// 5) Perplexity from histogram (one block, 1024 threads)
// ---------------------------------------------------------------------------
__global__ void perp_kernel(int q)
{
    __shared__ float red[1024];
    const int k = threadIdx.x;
    const float p = (float)g_hist[k] * (1.0f / (float)M_TOT);
    red[k] = p * logf(p + 1e-7f);
    __syncthreads();
    for (int off = 512; off > 0; off >>= 1) {
        if (k < off) red[k] += red[k + off];
        __syncthreads();
    }
    if (k == 0) g_perp[q] = expf(-red[0]);
}

// ---------------------------------------------------------------------------
// 6) Final quantized_out: gather-sum 6 codes per (b,t), write transposed (B,C,T)
// ---------------------------------------------------------------------------
__global__ void qout_kernel(const float* __restrict__ codebooks,
                            float* __restrict__ out)
{
    __shared__ float tile[32][33];   // [t-local][c-local]
    __shared__ int   sidx[Q_LAYERS][32];
    const int b  = blockIdx.z;
    const int c0 = blockIdx.y * 32;
    const int t0 = blockIdx.x * 32;
    const int tx = threadIdx.x;
    const int ty = threadIdx.y;
    const int tid = ty * 32 + tx;

    if (tid < Q_LAYERS * 32) {
        const int q = tid >> 5, t = tid & 31;
        sidx[q][t] = g_idx[q * M_TOT + b * T_DIM + t0 + t];
    }
    __syncthreads();

#pragma unroll
    for (int i = ty; i < 32; i += 8) {   // i = t-local ; tx = c-local (coalesced reads)
        float s = 0.0f;
#pragma unroll
        for (int q = 0; q < Q_LAYERS; ++q)
            s += codebooks[((size_t)q * K_CODES + sidx[q][i]) * C_DIM + c0 + tx];
        tile[i][tx] = s;
    }
    __syncthreads();

    float* op = out + (size_t)b * C_DIM * T_DIM;
#pragma unroll
    for (int i = ty; i < 32; i += 8)     // i = c-local ; tx = t-local (coalesced writes)
        op[(size_t)(c0 + i) * T_DIM + t0 + tx] = tile[tx][i];
}

// ---------------------------------------------------------------------------
// 7) Indices out (B,T,Q) flattened as float, and scalar losses
// ---------------------------------------------------------------------------
__global__ void idx_out_kernel(float* __restrict__ out)
{
    const int i = blockIdx.x * blockDim.x + threadIdx.x;
    if (i >= OUT_IDX_ELEMS) return;
    const int m = i / Q_LAYERS;
    const int q = i - m * Q_LAYERS;
    out[OUT_QOUT_ELEMS + i] = (float)g_idx[q * M_TOT + m];
}

__global__ void scalar_out_kernel(float* __restrict__ out)
{
    if (threadIdx.x == 0) {
        double cs = 0.0;
        float  ps = 0.0f;
        for (int q = 0; q < Q_LAYERS; ++q) {
            cs += g_commit[q] / (double)((double)M_TOT * (double)C_DIM);
            ps += g_perp[q];
        }
        out[OUT_QOUT_ELEMS + OUT_IDX_ELEMS + 0] = (float)(cs / (double)Q_LAYERS);
        out[OUT_QOUT_ELEMS + OUT_IDX_ELEMS + 1] = ps / (float)Q_LAYERS;
    }
}

// ---------------------------------------------------------------------------
extern "C" void kernel_launch(void* const* d_in, const int* in_sizes, int n_in,
                              void* d_out, int out_size)
{
    const float* x         = (const float*)d_in[0];
    const float* codebooks = (const float*)d_in[1];
    float* out = (float*)d_out;
    (void)in_sizes; (void)n_in; (void)out_size;

    transpose_in_kernel<<<dim3(T_DIM / 32, C_DIM / 32, B_DIM), dim3(32, 8)>>>(x);

    for (int q = 0; q < Q_LAYERS; ++q) {
        const float* cb = codebooks + (size_t)q * K_CODES * C_DIM;
        norms_init_kernel<<<K_CODES, 128>>>(cb, q);
        gemm_argmin_kernel<<<M_TOT / 64, 256>>>(cb, q);
        update_kernel<<<M_TOT, 128>>>(cb, q);
        perp_kernel<<<1, 1024>>>(q);
    }

    qout_kernel<<<dim3(T_DIM / 32, C_DIM / 32, B_DIM), dim3(32, 8)>>>(codebooks, out);
    idx_out_kernel<<<(OUT_IDX_ELEMS + 255) / 256, 256>>>(out);
    scalar_out_kernel<<<1, 32>>>(out);
}

// round 3
// speedup vs baseline: 2.1824x; 2.1824x over previous
#include <cuda_runtime.h>
#include <cstdint>

// ---------------- problem constants ----------------
#define B_DIM    64
#define C_DIM    512
#define T_DIM    256
#define Q_LAYERS 6
#define K_CODES  1024
#define M_TOT    (B_DIM * T_DIM)                    // 16384
#define OUT_QOUT_ELEMS (B_DIM * C_DIM * T_DIM)      // 8388608
#define OUT_IDX_ELEMS  (B_DIM * T_DIM * Q_LAYERS)   // 98304

// ---------------- GEMM tiling ----------------
#define M_TILE   128                 // rows per CTA
#define N_TILE   128                 // codes per accumulation pass
#define N_PASSES (K_CODES / N_TILE)  // 8
#define KC       32                  // fp32 k-elems per staged chunk
#define K_CHUNKS (C_DIM / KC)        // 16
#define PADW     4
#define STR      (KC + PADW)         // 36 words per row
#define TILE_WORDS (128 * STR)       // per buffer per matrix
#define SMEM_BYTES (2 * 2 * TILE_WORDS * 4)   // 73728

// ---------------- device scratch (no allocation allowed) ----------------
__device__ float  g_X[M_TOT * C_DIM];          // residual (M, C) row-major
__device__ int    g_idx[Q_LAYERS * M_TOT];
__device__ int    g_cand[M_TOT * 4];           // per-row top-4 tf32 candidates
__device__ float  g_norm[Q_LAYERS * K_CODES];  // code norms (all layers)
__device__ int    g_hist[K_CODES];
__device__ double g_commit[Q_LAYERS];
__device__ float  g_perp[Q_LAYERS];

// ---------------- helpers ----------------
__device__ __forceinline__ uint32_t smem_u32(const void* p) {
    uint32_t a;
    asm("{ .reg .u64 t; cvta.to.shared.u64 t, %1; cvt.u32.u64 %0, t; }" : "=r"(a) : "l"(p));
    return a;
}
__device__ __forceinline__ void cp_async16(uint32_t dst, const void* src) {
    asm volatile("cp.async.cg.shared.global [%0], [%1], 16;" :: "r"(dst), "l"(src));
}
__device__ __forceinline__ void cp_commit() {
    asm volatile("cp.async.commit_group;" ::: "memory");
}
template <int N> __device__ __forceinline__ void cp_wait() {
    asm volatile("cp.async.wait_group %0;" :: "n"(N) : "memory");
}

__device__ __forceinline__ void mma_tf32(float* c, const uint32_t* a,
                                         uint32_t b0, uint32_t b1) {
    asm volatile(
        "mma.sync.aligned.m16n8k8.row.col.f32.tf32.tf32.f32 "
        "{%0,%1,%2,%3}, {%4,%5,%6,%7}, {%8,%9}, {%0,%1,%2,%3};"
        : "+f"(c[0]), "+f"(c[1]), "+f"(c[2]), "+f"(c[3])
        : "r"(a[0]), "r"(a[1]), "r"(a[2]), "r"(a[3]), "r"(b0), "r"(b1));
}

// fast top-4 insert (strict <; scan order gives first-min tiebreak within a lane)
__device__ __forceinline__ void ins4(float s, int n, float v[4], int ix[4]) {
    if (s < v[3]) {
        if (s < v[1]) {
            if (s < v[0]) { v[3]=v[2];ix[3]=ix[2]; v[2]=v[1];ix[2]=ix[1];
                            v[1]=v[0];ix[1]=ix[0]; v[0]=s;ix[0]=n; }
            else          { v[3]=v[2];ix[3]=ix[2]; v[2]=v[1];ix[2]=ix[1];
                            v[1]=s;ix[1]=n; }
        } else {
            if (s < v[2]) { v[3]=v[2];ix[3]=ix[2]; v[2]=s;ix[2]=n; }
            else          { v[3]=s;ix[3]=n; }
        }
    }
}
// lexicographic insert for cross-lane merges ((value, index) order)
__device__ __forceinline__ bool lexlt(float s, int n, float v, int i) {
    return (s < v) || (s == v && n < i);
}
__device__ __forceinline__ void ins4lex(float s, int n, float v[4], int ix[4]) {
    if (lexlt(s, n, v[3], ix[3])) {
        if (lexlt(s, n, v[1], ix[1])) {
            if (lexlt(s, n, v[0], ix[0])) { v[3]=v[2];ix[3]=ix[2]; v[2]=v[1];ix[2]=ix[1];
                                            v[1]=v[0];ix[1]=ix[0]; v[0]=s;ix[0]=n; }
            else                          { v[3]=v[2];ix[3]=ix[2]; v[2]=v[1];ix[2]=ix[1];
                                            v[1]=s;ix[1]=n; }
        } else {
            if (lexlt(s, n, v[2], ix[2])) { v[3]=v[2];ix[3]=ix[2]; v[2]=s;ix[2]=n; }
            else                          { v[3]=s;ix[3]=n; }
        }
    }
}

// ---------------------------------------------------------------------------
// 1) Transpose input x (B, C, T) -> g_X (B*T, C)
// ---------------------------------------------------------------------------
__global__ void transpose_in_kernel(const float* __restrict__ x)
{
    __shared__ float tile[32][33];
    const int b  = blockIdx.z;
    const int c0 = blockIdx.y * 32;
    const int t0 = blockIdx.x * 32;
    const int tx = threadIdx.x;
    const int ty = threadIdx.y;

    const float* xp = x + (size_t)b * C_DIM * T_DIM;
#pragma unroll
    for (int i = ty; i < 32; i += 8)
        tile[i][tx] = xp[(size_t)(c0 + i) * T_DIM + t0 + tx];
    __syncthreads();
#pragma unroll
    for (int i = ty; i < 32; i += 8)
        g_X[(size_t)(b * T_DIM + t0 + i) * C_DIM + c0 + tx] = tile[tx][i];
}

// ---------------------------------------------------------------------------
// 2) Code norms for all layers + zero commit accumulators
// ---------------------------------------------------------------------------
__global__ void norms_all_kernel(const float* __restrict__ codebooks)
{
    __shared__ float red[128];
    const int gk  = blockIdx.x;                 // 0 .. 6*1024-1
    const int tid = threadIdx.x;
    const float4 c = reinterpret_cast<const float4*>(codebooks + (size_t)gk * C_DIM)[tid];
    red[tid] = c.x * c.x + c.y * c.y + c.z * c.z + c.w * c.w;
    __syncthreads();
    for (int off = 64; off > 0; off >>= 1) {
        if (tid < off) red[tid] += red[tid + off];
        __syncthreads();
    }
    if (tid == 0) {
        g_norm[gk] = red[0];
        if (gk < Q_LAYERS) g_commit[gk] = 0.0;
    }
}

// ---------------------------------------------------------------------------
// 3) tf32 mma.sync GEMM + top-4 argmin candidates.
//    grid = 128 CTAs (128 rows), block = 128 threads (4 warps x 32 rows).
// ---------------------------------------------------------------------------
__device__ __forceinline__ void stage_chunk(uint32_t abase, uint32_t bbase,
                                            int buf, int kc, int m0,
                                            const float* __restrict__ cbn0,
                                            int tid)
{
    // A: 128 rows x 32 floats, thread = row
    const float* asrc = g_X + (size_t)(m0 + tid) * C_DIM + kc * KC;
    const uint32_t ad = abase + (uint32_t)(buf * TILE_WORDS + tid * STR) * 4u;
#pragma unroll
    for (int g = 0; g < 8; ++g) cp_async16(ad + g * 16, asrc + g * 4);
    // B: 128 rows x 32 floats, thread = row
    const float* bsrc = cbn0 + (size_t)tid * C_DIM + kc * KC;
    const uint32_t bd = bbase + (uint32_t)(buf * TILE_WORDS + tid * STR) * 4u;
#pragma unroll
    for (int g = 0; g < 8; ++g) cp_async16(bd + g * 16, bsrc + g * 4);
}

__global__ __launch_bounds__(128, 1) void gemm_mma_kernel(
    const float* __restrict__ cb, int q)
{
    extern __shared__ float sm[];
    float* As = sm;                       // [2][128][STR]
    float* Bs = sm + 2 * TILE_WORDS;      // [2][128][STR]
    const uint32_t abase = smem_u32(As);
    const uint32_t bbase = smem_u32(Bs);

    const int tid  = threadIdx.x;
    const int wid  = tid >> 5;
    const int lane = tid & 31;
    const int lg   = lane >> 2;      // 0..7 (group)
    const int lt   = lane & 3;       // 0..3 (thread-in-group)
    const int m0   = blockIdx.x * M_TILE;

    // top-4 per row-slot: slot = s*2 + h -> row = wid*32 + s*16 + h*8 + lg
    float v[4][4];
    int   ix[4][4];
#pragma unroll
    for (int r = 0; r < 4; ++r)
#pragma unroll
        for (int j = 0; j < 4; ++j) { v[r][j] = 3.4e38f; ix[r][j] = 0; }

    const float* __restrict__ norms = g_norm + q * K_CODES;

    for (int nt = 0; nt < N_PASSES; ++nt) {
        const int n0 = nt * N_TILE;
        const float* cbn0 = cb + (size_t)n0 * C_DIM;

        float acc[2][16][4];
#pragma unroll
        for (int s = 0; s < 2; ++s)
#pragma unroll
            for (int ns = 0; ns < 16; ++ns)
#pragma unroll
                for (int j = 0; j < 4; ++j) acc[s][ns][j] = 0.0f;

        stage_chunk(abase, bbase, 0, 0, m0, cbn0, tid);
        cp_commit();

#pragma unroll 1
        for (int kc = 0; kc < K_CHUNKS; ++kc) {
            const int buf = kc & 1;
            if (kc + 1 < K_CHUNKS) {
                stage_chunk(abase, bbase, buf ^ 1, kc + 1, m0, cbn0, tid);
                cp_commit();
                cp_wait<1>();
            } else {
                cp_wait<0>();
            }
            __syncthreads();                    // chunk `buf` ready for all

            const float* Ab = As + buf * TILE_WORDS;
            const float* Bb = Bs + buf * TILE_WORDS;

#pragma unroll 1
            for (int ks = 0; ks < 4; ++ks) {
                const int k = ks * 8;
                uint32_t a[2][4];
#pragma unroll
                for (int s = 0; s < 2; ++s) {
                    const int rb = wid * 32 + s * 16;
                    a[s][0] = __float_as_uint(Ab[(rb + lg    ) * STR + k + lt    ]);
                    a[s][1] = __float_as_uint(Ab[(rb + lg + 8) * STR + k + lt    ]);
                    a[s][2] = __float_as_uint(Ab[(rb + lg    ) * STR + k + lt + 4]);
                    a[s][3] = __float_as_uint(Ab[(rb + lg + 8) * STR + k + lt + 4]);
                }
#pragma unroll
                for (int ns = 0; ns < 16; ++ns) {
                    const uint32_t b0 = __float_as_uint(Bb[(ns * 8 + lg) * STR + k + lt    ]);
                    const uint32_t b1 = __float_as_uint(Bb[(ns * 8 + lg) * STR + k + lt + 4]);
                    mma_tf32(acc[0][ns], a[0], b0, b1);
                    mma_tf32(acc[1][ns], a[1], b0, b1);
                }
            }
            __syncthreads();                    // all reads of `buf` done
        }

        // epilogue: score = norm[n] - 2*dot; insert into per-row top-4
#pragma unroll
        for (int s = 0; s < 2; ++s) {
#pragma unroll
            for (int ns = 0; ns < 16; ++ns) {
                const int n = n0 + ns * 8 + lt * 2;
                const float nm0 = __ldg(&norms[n]);
                const float nm1 = __ldg(&norms[n + 1]);
                ins4(fmaf(-2.0f, acc[s][ns][0], nm0), n,     v[s*2+0], ix[s*2+0]);
                ins4(fmaf(-2.0f, acc[s][ns][1], nm1), n + 1, v[s*2+0], ix[s*2+0]);
                ins4(fmaf(-2.0f, acc[s][ns][2], nm0), n,     v[s*2+1], ix[s*2+1]);
                ins4(fmaf(-2.0f, acc[s][ns][3], nm1), n + 1, v[s*2+1], ix[s*2+1]);
            }
        }
    }

    // merge top-4 across the 4 lanes (lt = 0..3) sharing each row
#pragma unroll
    for (int r = 0; r < 4; ++r) {
#pragma unroll
        for (int o = 1; o <= 2; o <<= 1) {
            float ov[4]; int oi[4];
#pragma unroll
            for (int j = 0; j < 4; ++j) {
                ov[j] = __shfl_xor_sync(0xffffffffu, v[r][j], o);
                oi[j] = __shfl_xor_sync(0xffffffffu, ix[r][j], o);
            }
#pragma unroll
            for (int j = 0; j < 4; ++j) ins4lex(ov[j], oi[j], v[r], ix[r]);
        }
        if (lt == 0) {
            const int row = m0 + wid * 32 + (r >> 1) * 16 + (r & 1) * 8 + lg;
#pragma unroll
            for (int j = 0; j < 4; ++j) g_cand[row * 4 + j] = ix[r][j];
        }
    }
}

// ---------------------------------------------------------------------------
// 4) Exact fp32 re-rank of the 4 candidates + residual update + commit + hist
// ---------------------------------------------------------------------------
__global__ __launch_bounds__(128) void fixup_update_kernel(
    const float* __restrict__ cb, int q)
{
    __shared__ float s_d[4][4];
    __shared__ int   s_choice;
    const int m   = blockIdx.x;
    const int tid = threadIdx.x;
    const int wid = tid >> 5;
    const int lid = tid & 31;

    int cand[4];
#pragma unroll
    for (int c = 0; c < 4; ++c) cand[c] = g_cand[m * 4 + c];

    const float4 xr = reinterpret_cast<const float4*>(g_X + (size_t)m * C_DIM)[tid];
    float4 cc[4];
    float  d[4];
#pragma unroll
    for (int c = 0; c < 4; ++c) {
        cc[c] = reinterpret_cast<const float4*>(cb + (size_t)cand[c] * C_DIM)[tid];
        const float dx = xr.x - cc[c].x, dy = xr.y - cc[c].y;
        const float dz = xr.z - cc[c].z, dw = xr.w - cc[c].w;
        d[c] = dx * dx + dy * dy + dz * dz + dw * dw;
    }
#pragma unroll
    for (int c = 0; c < 4; ++c) {
#pragma unroll
        for (int o = 16; o > 0; o >>= 1) d[c] += __shfl_xor_sync(0xffffffffu, d[c], o);
        if (lid == 0) s_d[wid][c] = d[c];
    }
    __syncthreads();
    if (tid == 0) {
        float best = 3.4e38f; int bi = 0x7fffffff, bc = 0;
#pragma unroll
        for (int c = 0; c < 4; ++c) {
            const float dv = s_d[0][c] + s_d[1][c] + s_d[2][c] + s_d[3][c];
            const int   cx = cand[c];
            if (dv < best || (dv == best && cx < bi)) { best = dv; bi = cx; bc = c; }
        }
        s_choice = bc;
        g_idx[q * M_TOT + m] = bi;
        atomicAdd(&g_commit[q], (double)best);
        atomicAdd(&g_hist[bi], 1);
    }
    __syncthreads();
    const int c = s_choice;
    float4 r;
    r.x = xr.x - cc[c].x; r.y = xr.y - cc[c].y;
    r.z = xr.z - cc[c].z; r.w = xr.w - cc[c].w;
    reinterpret_cast<float4*>(g_X + (size_t)m * C_DIM)[tid] = r;
}

// ---------------------------------------------------------------------------
// 5) Perplexity from histogram (re-zeroes histogram for next layer/replay)
// ---------------------------------------------------------------------------
__global__ void perp_kernel(int q)
{
    __shared__ float red[1024];
    const int k = threadIdx.x;
    const float p = (float)g_hist[k] * (1.0f / (float)M_TOT);
    g_hist[k] = 0;
    red[k] = p * logf(p + 1e-7f);
    __syncthreads();
    for (int off = 512; off > 0; off >>= 1) {
        if (k < off) red[k] += red[k + off];
        __syncthreads();
    }
    if (k == 0) g_perp[q] = expf(-red[0]);
}

// ---------------------------------------------------------------------------
// 6) quantized_out: gather-sum 6 codes per (b,t), write transposed (B,C,T)
// ---------------------------------------------------------------------------
__global__ void qout_kernel(const float* __restrict__ codebooks,
                            float* __restrict__ out)
{
    __shared__ float tile[32][33];
    __shared__ int   sidx[Q_LAYERS][32];
    const int b  = blockIdx.z;
    const int c0 = blockIdx.y * 32;
    const int t0 = blockIdx.x * 32;
    const int tx = threadIdx.x;
    const int ty = threadIdx.y;
    const int tid = ty * 32 + tx;

    if (tid < Q_LAYERS * 32) {
        const int q = tid >> 5, t = tid & 31;
        sidx[q][t] = g_idx[q * M_TOT + b * T_DIM + t0 + t];
    }
    __syncthreads();

#pragma unroll
    for (int i = ty; i < 32; i += 8) {
        float s = 0.0f;
#pragma unroll
        for (int q = 0; q < Q_LAYERS; ++q)
            s += codebooks[((size_t)q * K_CODES + sidx[q][i]) * C_DIM + c0 + tx];
        tile[i][tx] = s;
    }
    __syncthreads();

    float* op = out + (size_t)b * C_DIM * T_DIM;
#pragma unroll
    for (int i = ty; i < 32; i += 8)
        op[(size_t)(c0 + i) * T_DIM + t0 + tx] = tile[tx][i];
}

// ---------------------------------------------------------------------------
// 7) Index output (B,T,Q) as float, and scalar losses
// ---------------------------------------------------------------------------
__global__ void idx_out_kernel(float* __restrict__ out)
{
    const int i = blockIdx.x * blockDim.x + threadIdx.x;
    if (i >= OUT_IDX_ELEMS) return;
    const int m = i / Q_LAYERS;
    const int q = i - m * Q_LAYERS;
    out[OUT_QOUT_ELEMS + i] = (float)g_idx[q * M_TOT + m];
}

__global__ void scalar_out_kernel(float* __restrict__ out)
{
    if (threadIdx.x == 0) {
        double cs = 0.0;
        float  ps = 0.0f;
        for (int q = 0; q < Q_LAYERS; ++q) {
            cs += g_commit[q] / (double)((double)M_TOT * (double)C_DIM);
            ps += g_perp[q];
        }
        out[OUT_QOUT_ELEMS + OUT_IDX_ELEMS + 0] = (float)(cs / (double)Q_LAYERS);
        out[OUT_QOUT_ELEMS + OUT_IDX_ELEMS + 1] = ps / (float)Q_LAYERS;
    }
}

// ---------------------------------------------------------------------------
extern "C" void kernel_launch(void* const* d_in, const int* in_sizes, int n_in,
                              void* d_out, int out_size)
{
    const float* x         = (const float*)d_in[0];
    const float* codebooks = (const float*)d_in[1];
    float* out = (float*)d_out;
    (void)in_sizes; (void)n_in; (void)out_size;

    static bool attr_set = false;
    if (!attr_set) {
        cudaFuncSetAttribute(gemm_mma_kernel,
                             cudaFuncAttributeMaxDynamicSharedMemorySize, SMEM_BYTES);
        attr_set = true;
    }

    transpose_in_kernel<<<dim3(T_DIM / 32, C_DIM / 32, B_DIM), dim3(32, 8)>>>(x);
    norms_all_kernel<<<Q_LAYERS * K_CODES, 128>>>(codebooks);

    for (int q = 0; q < Q_LAYERS; ++q) {
        const float* cb = codebooks + (size_t)q * K_CODES * C_DIM;
        gemm_mma_kernel<<<M_TOT / M_TILE, 128, SMEM_BYTES>>>(cb, q);
        fixup_update_kernel<<<M_TOT, 128>>>(cb, q);
        perp_kernel<<<1, 1024>>>(q);
    }

    qout_kernel<<<dim3(T_DIM / 32, C_DIM / 32, B_DIM), dim3(32, 8)>>>(codebooks, out);
    idx_out_kernel<<<(OUT_IDX_ELEMS + 255) / 256, 256>>>(out);
    scalar_out_kernel<<<1, 32>>>(out);
}

// round 4
// speedup vs baseline: 3.7506x; 1.7186x over previous
#include <cuda_runtime.h>
#include <cstdint>

// ---------------- problem constants ----------------
#define B_DIM    64
#define C_DIM    512
#define T_DIM    256
#define Q_LAYERS 6
#define K_CODES  1024
#define M_TOT    (B_DIM * T_DIM)                    // 16384
#define OUT_QOUT_ELEMS (B_DIM * C_DIM * T_DIM)      // 8388608
#define OUT_IDX_ELEMS  (B_DIM * T_DIM * Q_LAYERS)   // 98304

// ---------------- GEMM tiling ----------------
#define M_TILE   128                 // rows per CTA
#define N_TILE   256                 // codes per accumulation pass
#define N_PASSES (K_CODES / N_TILE)  // 4
#define KC       32                  // fp32 k-elems per staged chunk
#define K_CHUNKS (C_DIM / KC)        // 16
#define STAGES   3
#define PADW     4
#define STR      (KC + PADW)         // 36 words per row
#define A_WORDS  (M_TILE * STR)      // 4608
#define B_WORDS  (N_TILE * STR)      // 9216
#define STAGE_WORDS (A_WORDS + B_WORDS)              // 13824
#define SMEM_BYTES (STAGES * STAGE_WORDS * 4)        // 165888

// ---------------- device scratch ----------------
__device__ float  g_X[M_TOT * C_DIM];          // residual (M, C) row-major
__device__ int    g_idx[Q_LAYERS * M_TOT];
__device__ int    g_cand[M_TOT * 4];
__device__ float  g_norm[Q_LAYERS * K_CODES];
__device__ int    g_hist[K_CODES];
__device__ double g_commit[Q_LAYERS];
__device__ float  g_perp[Q_LAYERS];

// ---------------- helpers ----------------
__device__ __forceinline__ uint32_t smem_u32(const void* p) {
    uint32_t a;
    asm("{ .reg .u64 t; cvta.to.shared.u64 t, %1; cvt.u32.u64 %0, t; }" : "=r"(a) : "l"(p));
    return a;
}
__device__ __forceinline__ void cp_async16(uint32_t dst, const void* src) {
    asm volatile("cp.async.cg.shared.global [%0], [%1], 16;" :: "r"(dst), "l"(src));
}
__device__ __forceinline__ void cp_commit() {
    asm volatile("cp.async.commit_group;" ::: "memory");
}
template <int N> __device__ __forceinline__ void cp_wait() {
    asm volatile("cp.async.wait_group %0;" :: "n"(N) : "memory");
}

__device__ __forceinline__ void mma_tf32(float* c, const uint32_t* a,
                                         uint32_t b0, uint32_t b1) {
    asm volatile(
        "mma.sync.aligned.m16n8k8.row.col.f32.tf32.tf32.f32 "
        "{%0,%1,%2,%3}, {%4,%5,%6,%7}, {%8,%9}, {%0,%1,%2,%3};"
        : "+f"(c[0]), "+f"(c[1]), "+f"(c[2]), "+f"(c[3])
        : "r"(a[0]), "r"(a[1]), "r"(a[2]), "r"(a[3]), "r"(b0), "r"(b1));
}

// strict-< top-4 insert (ascending-n scan => first-min kept)
__device__ __forceinline__ void ins4(float s, int n, float v[4], int ix[4]) {
    if (s < v[3]) {
        if (s < v[1]) {
            if (s < v[0]) { v[3]=v[2];ix[3]=ix[2]; v[2]=v[1];ix[2]=ix[1];
                            v[1]=v[0];ix[1]=ix[0]; v[0]=s;ix[0]=n; }
            else          { v[3]=v[2];ix[3]=ix[2]; v[2]=v[1];ix[2]=ix[1];
                            v[1]=s;ix[1]=n; }
        } else {
            if (s < v[2]) { v[3]=v[2];ix[3]=ix[2]; v[2]=s;ix[2]=n; }
            else          { v[3]=s;ix[3]=n; }
        }
    }
}
__device__ __forceinline__ bool lexlt(float s, int n, float v, int i) {
    return (s < v) || (s == v && n < i);
}
__device__ __forceinline__ void ins4lex(float s, int n, float v[4], int ix[4]) {
    if (lexlt(s, n, v[3], ix[3])) {
        if (lexlt(s, n, v[1], ix[1])) {
            if (lexlt(s, n, v[0], ix[0])) { v[3]=v[2];ix[3]=ix[2]; v[2]=v[1];ix[2]=ix[1];
                                            v[1]=v[0];ix[1]=ix[0]; v[0]=s;ix[0]=n; }
            else                          { v[3]=v[2];ix[3]=ix[2]; v[2]=v[1];ix[2]=ix[1];
                                            v[1]=s;ix[1]=n; }
        } else {
            if (lexlt(s, n, v[2], ix[2])) { v[3]=v[2];ix[3]=ix[2]; v[2]=s;ix[2]=n; }
            else                          { v[3]=s;ix[3]=n; }
        }
    }
}

// ---------------------------------------------------------------------------
// 1) Transpose input x (B, C, T) -> g_X (B*T, C)
// ---------------------------------------------------------------------------
__global__ void transpose_in_kernel(const float* __restrict__ x)
{
    __shared__ float tile[32][33];
    const int b  = blockIdx.z;
    const int c0 = blockIdx.y * 32;
    const int t0 = blockIdx.x * 32;
    const int tx = threadIdx.x;
    const int ty = threadIdx.y;

    const float* xp = x + (size_t)b * C_DIM * T_DIM;
#pragma unroll
    for (int i = ty; i < 32; i += 8)
        tile[i][tx] = xp[(size_t)(c0 + i) * T_DIM + t0 + tx];
    __syncthreads();
#pragma unroll
    for (int i = ty; i < 32; i += 8)
        g_X[(size_t)(b * T_DIM + t0 + i) * C_DIM + c0 + tx] = tile[tx][i];
}

// ---------------------------------------------------------------------------
// 2) Code norms for all layers + zero commit accumulators
// ---------------------------------------------------------------------------
__global__ void norms_all_kernel(const float* __restrict__ codebooks)
{
    __shared__ float red[128];
    const int gk  = blockIdx.x;
    const int tid = threadIdx.x;
    const float4 c = reinterpret_cast<const float4*>(codebooks + (size_t)gk * C_DIM)[tid];
    red[tid] = c.x * c.x + c.y * c.y + c.z * c.z + c.w * c.w;
    __syncthreads();
    for (int off = 64; off > 0; off >>= 1) {
        if (tid < off) red[tid] += red[tid + off];
        __syncthreads();
    }
    if (tid == 0) {
        g_norm[gk] = red[0];
        if (gk < Q_LAYERS) g_commit[gk] = 0.0;
    }
}

// ---------------------------------------------------------------------------
// 3) tf32 mma.sync GEMM + top-4 argmin candidates.
//    grid = 128 CTAs, block = 256 threads (8 warps: 4 row-groups x 2 n-groups)
// ---------------------------------------------------------------------------
__device__ __forceinline__ void stage_chunk(uint32_t sbase, int buf, int kc,
                                            int m0, const float* __restrict__ cb,
                                            int tid)
{
    const int kw = kc * KC;
    const uint32_t ab = sbase + (uint32_t)(buf * STAGE_WORDS) * 4u;
    const uint32_t bb = ab + (uint32_t)A_WORDS * 4u;
    // A: 128 rows x 8 units
#pragma unroll
    for (int i = 0; i < 4; ++i) {
        const int idx = tid + 256 * i;
        const int row = idx >> 3, g = idx & 7;
        cp_async16(ab + (uint32_t)(row * STR + g * 4) * 4u,
                   g_X + (size_t)(m0 + row) * C_DIM + kw + g * 4);
    }
    // B: 256 rows x 8 units
#pragma unroll
    for (int i = 0; i < 8; ++i) {
        const int idx = tid + 256 * i;
        const int row = idx >> 3, g = idx & 7;
        cp_async16(bb + (uint32_t)(row * STR + g * 4) * 4u,
                   cb + (size_t)row * C_DIM + kw + g * 4);
    }
}

__global__ __launch_bounds__(256, 1) void gemm_mma_kernel(
    const float* __restrict__ cb, int q)
{
    extern __shared__ float sm[];
    const uint32_t sbase = smem_u32(sm);

    const int tid  = threadIdx.x;
    const int wid  = tid >> 5;
    const int lane = tid & 31;
    const int wr   = wid & 3;        // row group: rows wr*32 .. +31
    const int wc   = wid >> 2;       // n group: codes wc*128 .. +127 within pass
    const int lg   = lane >> 2;      // 0..7
    const int lt   = lane & 3;       // 0..3
    const int m0   = blockIdx.x * M_TILE;

    float v[4][4];
    int   ix[4][4];
#pragma unroll
    for (int r = 0; r < 4; ++r)
#pragma unroll
        for (int j = 0; j < 4; ++j) { v[r][j] = 3.4e38f; ix[r][j] = 0; }

    const float* __restrict__ norms = g_norm + q * K_CODES;

    for (int nt = 0; nt < N_PASSES; ++nt) {
        const int n0 = nt * N_TILE;
        const float* cbn0 = cb + (size_t)n0 * C_DIM;

        float acc[2][16][4];
#pragma unroll
        for (int s = 0; s < 2; ++s)
#pragma unroll
            for (int ns = 0; ns < 16; ++ns)
#pragma unroll
                for (int j = 0; j < 4; ++j) acc[s][ns][j] = 0.0f;

        __syncthreads();                        // stage bufs free (prev pass done)
        stage_chunk(sbase, 0, 0, m0, cbn0, tid); cp_commit();
        stage_chunk(sbase, 1, 1, m0, cbn0, tid); cp_commit();

#pragma unroll 1
        for (int kc = 0; kc < K_CHUNKS; ++kc) {
            if (kc == K_CHUNKS - 1) cp_wait<0>(); else cp_wait<1>();
            __syncthreads();                    // chunk kc visible to all
            if (kc + 2 < K_CHUNKS) {
                stage_chunk(sbase, (kc + 2) % STAGES, kc + 2, m0, cbn0, tid);
                cp_commit();
            }

            const float* Ab = sm + (kc % STAGES) * STAGE_WORDS;
            const float* Bb = Ab + A_WORDS;

#pragma unroll
            for (int ks = 0; ks < 4; ++ks) {
                const int k = ks * 8;
                uint32_t a[2][4];
#pragma unroll
                for (int s = 0; s < 2; ++s) {
                    const int rb = wr * 32 + s * 16;
                    a[s][0] = __float_as_uint(Ab[(rb + lg    ) * STR + k + lt    ]);
                    a[s][1] = __float_as_uint(Ab[(rb + lg + 8) * STR + k + lt    ]);
                    a[s][2] = __float_as_uint(Ab[(rb + lg    ) * STR + k + lt + 4]);
                    a[s][3] = __float_as_uint(Ab[(rb + lg + 8) * STR + k + lt + 4]);
                }
#pragma unroll
                for (int ns = 0; ns < 16; ++ns) {
                    const int nb = wc * 128 + ns * 8 + lg;
                    const uint32_t b0 = __float_as_uint(Bb[nb * STR + k + lt    ]);
                    const uint32_t b1 = __float_as_uint(Bb[nb * STR + k + lt + 4]);
                    mma_tf32(acc[0][ns], a[0], b0, b1);
                    mma_tf32(acc[1][ns], a[1], b0, b1);
                }
            }
        }

        // epilogue: score = ||cb||^2 - 2*dot; per-thread top-4 per row-slot
#pragma unroll
        for (int s = 0; s < 2; ++s) {
#pragma unroll
            for (int ns = 0; ns < 16; ++ns) {
                const int n = n0 + wc * 128 + ns * 8 + lt * 2;
                const float nm0 = __ldg(&norms[n]);
                const float nm1 = __ldg(&norms[n + 1]);
                ins4(fmaf(-2.0f, acc[s][ns][0], nm0), n,     v[s*2+0], ix[s*2+0]);
                ins4(fmaf(-2.0f, acc[s][ns][1], nm1), n + 1, v[s*2+0], ix[s*2+0]);
                ins4(fmaf(-2.0f, acc[s][ns][2], nm0), n,     v[s*2+1], ix[s*2+1]);
                ins4(fmaf(-2.0f, acc[s][ns][3], nm1), n + 1, v[s*2+1], ix[s*2+1]);
            }
        }
    }

    // merge across lt (4 lanes per row)
#pragma unroll
    for (int r = 0; r < 4; ++r) {
#pragma unroll
        for (int o = 1; o <= 2; o <<= 1) {
            float ov[4]; int oi[4];
#pragma unroll
            for (int j = 0; j < 4; ++j) {
                ov[j] = __shfl_xor_sync(0xffffffffu, v[r][j], o);
                oi[j] = __shfl_xor_sync(0xffffffffu, ix[r][j], o);
            }
#pragma unroll
            for (int j = 0; j < 4; ++j) ins4lex(ov[j], oi[j], v[r], ix[r]);
        }
    }

    // cross-warp merge (wc=0 vs wc=1) via smem (reuse stage buffers)
    float* smV = sm;                    // [2][128][4]
    int*   smI = (int*)(sm + 1024);     // [2][128][4]
    __syncthreads();                    // all compute done; safe to reuse smem
    if (lt == 0) {
#pragma unroll
        for (int r = 0; r < 4; ++r) {
            const int row = wr * 32 + (r >> 1) * 16 + (r & 1) * 8 + lg;
#pragma unroll
            for (int j = 0; j < 4; ++j) {
                smV[(wc * 128 + row) * 4 + j] = v[r][j];
                smI[(wc * 128 + row) * 4 + j] = ix[r][j];
            }
        }
    }
    __syncthreads();
    if (wid < 4) {
        const int row = wid * 32 + lane;
        float fv[4]; int fi[4];
#pragma unroll
        for (int j = 0; j < 4; ++j) { fv[j] = 3.4e38f; fi[j] = 0x7fffffff; }
#pragma unroll
        for (int h = 0; h < 2; ++h)
#pragma unroll
            for (int j = 0; j < 4; ++j)
                ins4lex(smV[(h * 128 + row) * 4 + j], smI[(h * 128 + row) * 4 + j], fv, fi);
#pragma unroll
        for (int j = 0; j < 4; ++j) g_cand[(m0 + row) * 4 + j] = fi[j];
    }
}

// ---------------------------------------------------------------------------
// 4) Exact fp32 re-rank of the 4 candidates + residual update + commit + hist
// ---------------------------------------------------------------------------
__global__ __launch_bounds__(128) void fixup_update_kernel(
    const float* __restrict__ cb, int q)
{
    __shared__ float s_d[4][4];
    __shared__ int   s_choice;
    const int m   = blockIdx.x;
    const int tid = threadIdx.x;
    const int wid = tid >> 5;
    const int lid = tid & 31;

    int cand[4];
#pragma unroll
    for (int c = 0; c < 4; ++c) cand[c] = g_cand[m * 4 + c];

    const float4 xr = reinterpret_cast<const float4*>(g_X + (size_t)m * C_DIM)[tid];
    float4 cc[4];
    float  d[4];
#pragma unroll
    for (int c = 0; c < 4; ++c) {
        cc[c] = reinterpret_cast<const float4*>(cb + (size_t)cand[c] * C_DIM)[tid];
        const float dx = xr.x - cc[c].x, dy = xr.y - cc[c].y;
        const float dz = xr.z - cc[c].z, dw = xr.w - cc[c].w;
        d[c] = dx * dx + dy * dy + dz * dz + dw * dw;
    }
#pragma unroll
    for (int c = 0; c < 4; ++c) {
#pragma unroll
        for (int o = 16; o > 0; o >>= 1) d[c] += __shfl_xor_sync(0xffffffffu, d[c], o);
        if (lid == 0) s_d[wid][c] = d[c];
    }
    __syncthreads();
    if (tid == 0) {
        float best = 3.4e38f; int bi = 0x7fffffff, bc = 0;
#pragma unroll
        for (int c = 0; c < 4; ++c) {
            const float dv = s_d[0][c] + s_d[1][c] + s_d[2][c] + s_d[3][c];
            const int   cx = cand[c];
            if (dv < best || (dv == best && cx < bi)) { best = dv; bi = cx; bc = c; }
        }
        s_choice = bc;
        g_idx[q * M_TOT + m] = bi;
        atomicAdd(&g_commit[q], (double)best);
        atomicAdd(&g_hist[bi], 1);
    }
    __syncthreads();
    const int c = s_choice;
    float4 r;
    r.x = xr.x - cc[c].x; r.y = xr.y - cc[c].y;
    r.z = xr.z - cc[c].z; r.w = xr.w - cc[c].w;
    reinterpret_cast<float4*>(g_X + (size_t)m * C_DIM)[tid] = r;
}

// ---------------------------------------------------------------------------
// 5) Perplexity from histogram (re-zeroes histogram for next layer/replay)
// ---------------------------------------------------------------------------
__global__ void perp_kernel(int q)
{
    __shared__ float red[1024];
    const int k = threadIdx.x;
    const float p = (float)g_hist[k] * (1.0f / (float)M_TOT);
    g_hist[k] = 0;
    red[k] = p * logf(p + 1e-7f);
    __syncthreads();
    for (int off = 512; off > 0; off >>= 1) {
        if (k < off) red[k] += red[k + off];
        __syncthreads();
    }
    if (k == 0) g_perp[q] = expf(-red[0]);
}

// ---------------------------------------------------------------------------
// 6) quantized_out: gather-sum 6 codes per (b,t), write transposed (B,C,T)
// ---------------------------------------------------------------------------
__global__ void qout_kernel(const float* __restrict__ codebooks,
                            float* __restrict__ out)
{
    __shared__ float tile[32][33];
    __shared__ int   sidx[Q_LAYERS][32];
    const int b  = blockIdx.z;
    const int c0 = blockIdx.y * 32;
    const int t0 = blockIdx.x * 32;
    const int tx = threadIdx.x;
    const int ty = threadIdx.y;
    const int tid = ty * 32 + tx;

    if (tid < Q_LAYERS * 32) {
        const int q = tid >> 5, t = tid & 31;
        sidx[q][t] = g_idx[q * M_TOT + b * T_DIM + t0 + t];
    }
    __syncthreads();

#pragma unroll
    for (int i = ty; i < 32; i += 8) {
        float s = 0.0f;
#pragma unroll
        for (int q = 0; q < Q_LAYERS; ++q)
            s += codebooks[((size_t)q * K_CODES + sidx[q][i]) * C_DIM + c0 + tx];
        tile[i][tx] = s;
    }
    __syncthreads();

    float* op = out + (size_t)b * C_DIM * T_DIM;
#pragma unroll
    for (int i = ty; i < 32; i += 8)
        op[(size_t)(c0 + i) * T_DIM + t0 + tx] = tile[tx][i];
}

// ---------------------------------------------------------------------------
// 7) Index output (B,T,Q) as float, and scalar losses
// ---------------------------------------------------------------------------
__global__ void idx_out_kernel(float* __restrict__ out)
{
    const int i = blockIdx.x * blockDim.x + threadIdx.x;
    if (i >= OUT_IDX_ELEMS) return;
    const int m = i / Q_LAYERS;
    const int q = i - m * Q_LAYERS;
    out[OUT_QOUT_ELEMS + i] = (float)g_idx[q * M_TOT + m];
}

__global__ void scalar_out_kernel(float* __restrict__ out)
{
    if (threadIdx.x == 0) {
        double cs = 0.0;
        float  ps = 0.0f;
        for (int q = 0; q < Q_LAYERS; ++q) {
            cs += g_commit[q] / (double)((double)M_TOT * (double)C_DIM);
            ps += g_perp[q];
        }
        out[OUT_QOUT_ELEMS + OUT_IDX_ELEMS + 0] = (float)(cs / (double)Q_LAYERS);
        out[OUT_QOUT_ELEMS + OUT_IDX_ELEMS + 1] = ps / (float)Q_LAYERS;
    }
}

// ---------------------------------------------------------------------------
extern "C" void kernel_launch(void* const* d_in, const int* in_sizes, int n_in,
                              void* d_out, int out_size)
{
    const float* x         = (const float*)d_in[0];
    const float* codebooks = (const float*)d_in[1];
    float* out = (float*)d_out;
    (void)in_sizes; (void)n_in; (void)out_size;

    static bool attr_set = false;
    if (!attr_set) {
        cudaFuncSetAttribute(gemm_mma_kernel,
                             cudaFuncAttributeMaxDynamicSharedMemorySize, SMEM_BYTES);
        attr_set = true;
    }

    transpose_in_kernel<<<dim3(T_DIM / 32, C_DIM / 32, B_DIM), dim3(32, 8)>>>(x);
    norms_all_kernel<<<Q_LAYERS * K_CODES, 128>>>(codebooks);

    for (int q = 0; q < Q_LAYERS; ++q) {
        const float* cb = codebooks + (size_t)q * K_CODES * C_DIM;
        gemm_mma_kernel<<<M_TOT / M_TILE, 256, SMEM_BYTES>>>(cb, q);
        fixup_update_kernel<<<M_TOT, 128>>>(cb, q);
        perp_kernel<<<1, 1024>>>(q);
    }

    qout_kernel<<<dim3(T_DIM / 32, C_DIM / 32, B_DIM), dim3(32, 8)>>>(codebooks, out);
    idx_out_kernel<<<(OUT_IDX_ELEMS + 255) / 256, 256>>>(out);
    scalar_out_kernel<<<1, 32>>>(out);
}

// round 5
// speedup vs baseline: 5.0120x; 1.3363x over previous
#include <cuda_runtime.h>
#include <cuda_bf16.h>
#include <cstdint>

// ---------------- problem constants ----------------
#define B_DIM    64
#define C_DIM    512
#define T_DIM    256
#define Q_LAYERS 6
#define K_CODES  1024
#define M_TOT    (B_DIM * T_DIM)                    // 16384
#define OUT_QOUT_ELEMS (B_DIM * C_DIM * T_DIM)      // 8388608
#define OUT_IDX_ELEMS  (B_DIM * T_DIM * Q_LAYERS)   // 98304

// ---------------- GEMM tiling (bf16) ----------------
#define M_TILE   128
#define N_TILE   256
#define N_PASSES (K_CODES / N_TILE)  // 4
#define KC       32                  // bf16 k-elems per staged chunk (64B/row)
#define K_CHUNKS (C_DIM / KC)        // 16
#define STAGES   3
#define ROWB     80                  // smem row stride bytes (40 bf16)
#define A_BYTES  (M_TILE * ROWB)     // 10240
#define B_BYTES  (N_TILE * ROWB)     // 20480
#define STAGE_BYTES (A_BYTES + B_BYTES)        // 30720
#define SMEM_BYTES  (STAGES * STAGE_BYTES)     // 92160

// ---------------- device scratch ----------------
__device__ __align__(16) float          g_X [M_TOT * C_DIM];
__device__ __align__(16) __nv_bfloat16  g_Xb[M_TOT * C_DIM];
__device__ __align__(16) __nv_bfloat16  g_CBb[Q_LAYERS * K_CODES * C_DIM];
__device__ int    g_idx[Q_LAYERS * M_TOT];
__device__ int    g_cand[M_TOT * 4];
__device__ float  g_norm[Q_LAYERS * K_CODES];
__device__ int    g_hist[K_CODES];
__device__ double g_commit[Q_LAYERS];
__device__ float  g_perp[Q_LAYERS];

// ---------------- helpers ----------------
__device__ __forceinline__ uint32_t smem_u32(const void* p) {
    uint32_t a;
    asm("{ .reg .u64 t; cvta.to.shared.u64 t, %1; cvt.u32.u64 %0, t; }" : "=r"(a) : "l"(p));
    return a;
}
__device__ __forceinline__ void cp_async16(uint32_t dst, const void* src) {
    asm volatile("cp.async.cg.shared.global [%0], [%1], 16;" :: "r"(dst), "l"(src));
}
__device__ __forceinline__ void cp_commit() {
    asm volatile("cp.async.commit_group;" ::: "memory");
}
template <int N> __device__ __forceinline__ void cp_wait() {
    asm volatile("cp.async.wait_group %0;" :: "n"(N) : "memory");
}
__device__ __forceinline__ void ldsm_x4(uint32_t& r0, uint32_t& r1,
                                        uint32_t& r2, uint32_t& r3, uint32_t addr) {
    asm volatile("ldmatrix.sync.aligned.m8n8.x4.shared.b16 {%0,%1,%2,%3}, [%4];"
                 : "=r"(r0), "=r"(r1), "=r"(r2), "=r"(r3) : "r"(addr));
}
__device__ __forceinline__ void mma_bf16(float* c, const uint32_t* a,
                                         uint32_t b0, uint32_t b1) {
    asm volatile(
        "mma.sync.aligned.m16n8k16.row.col.f32.bf16.bf16.f32 "
        "{%0,%1,%2,%3}, {%4,%5,%6,%7}, {%8,%9}, {%0,%1,%2,%3};"
        : "+f"(c[0]), "+f"(c[1]), "+f"(c[2]), "+f"(c[3])
        : "r"(a[0]), "r"(a[1]), "r"(a[2]), "r"(a[3]), "r"(b0), "r"(b1));
}

__device__ __forceinline__ void ins4(float s, int n, float v[4], int ix[4]) {
    if (s < v[3]) {
        if (s < v[1]) {
            if (s < v[0]) { v[3]=v[2];ix[3]=ix[2]; v[2]=v[1];ix[2]=ix[1];
                            v[1]=v[0];ix[1]=ix[0]; v[0]=s;ix[0]=n; }
            else          { v[3]=v[2];ix[3]=ix[2]; v[2]=v[1];ix[2]=ix[1];
                            v[1]=s;ix[1]=n; }
        } else {
            if (s < v[2]) { v[3]=v[2];ix[3]=ix[2]; v[2]=s;ix[2]=n; }
            else          { v[3]=s;ix[3]=n; }
        }
    }
}
__device__ __forceinline__ bool lexlt(float s, int n, float v, int i) {
    return (s < v) || (s == v && n < i);
}
__device__ __forceinline__ void ins4lex(float s, int n, float v[4], int ix[4]) {
    if (lexlt(s, n, v[3], ix[3])) {
        if (lexlt(s, n, v[1], ix[1])) {
            if (lexlt(s, n, v[0], ix[0])) { v[3]=v[2];ix[3]=ix[2]; v[2]=v[1];ix[2]=ix[1];
                                            v[1]=v[0];ix[1]=ix[0]; v[0]=s;ix[0]=n; }
            else                          { v[3]=v[2];ix[3]=ix[2]; v[2]=v[1];ix[2]=ix[1];
                                            v[1]=s;ix[1]=n; }
        } else {
            if (lexlt(s, n, v[2], ix[2])) { v[3]=v[2];ix[3]=ix[2]; v[2]=s;ix[2]=n; }
            else                          { v[3]=s;ix[3]=n; }
        }
    }
}

// ---------------------------------------------------------------------------
__global__ void transpose_in_kernel(const float* __restrict__ x)
{
    __shared__ float tile[32][33];
    const int b  = blockIdx.z;
    const int c0 = blockIdx.y * 32;
    const int t0 = blockIdx.x * 32;
    const int tx = threadIdx.x;
    const int ty = threadIdx.y;

    const float* xp = x + (size_t)b * C_DIM * T_DIM;
#pragma unroll
    for (int i = ty; i < 32; i += 8)
        tile[i][tx] = xp[(size_t)(c0 + i) * T_DIM + t0 + tx];
    __syncthreads();
#pragma unroll
    for (int i = ty; i < 32; i += 8) {
        const float vv = tile[tx][i];
        const size_t o = (size_t)(b * T_DIM + t0 + i) * C_DIM + c0 + tx;
        g_X[o]  = vv;
        g_Xb[o] = __float2bfloat16(vv);
    }
}

// ---------------------------------------------------------------------------
__global__ void norms_all_kernel(const float* __restrict__ codebooks)
{
    __shared__ float red[128];
    const int gk  = blockIdx.x;
    const int tid = threadIdx.x;
    const float4 c = reinterpret_cast<const float4*>(codebooks + (size_t)gk * C_DIM)[tid];
    red[tid] = c.x * c.x + c.y * c.y + c.z * c.z + c.w * c.w;

    __nv_bfloat162 h0 = {__float2bfloat16(c.x), __float2bfloat16(c.y)};
    __nv_bfloat162 h1 = {__float2bfloat16(c.z), __float2bfloat16(c.w)};
    __nv_bfloat162* dst = reinterpret_cast<__nv_bfloat162*>(g_CBb + (size_t)gk * C_DIM);
    dst[tid * 2]     = h0;
    dst[tid * 2 + 1] = h1;

    __syncthreads();
    for (int off = 64; off > 0; off >>= 1) {
        if (tid < off) red[tid] += red[tid + off];
        __syncthreads();
    }
    if (tid == 0) {
        g_norm[gk] = red[0];
        if (gk < Q_LAYERS) g_commit[gk] = 0.0;
    }
}

// ---------------------------------------------------------------------------
__device__ __forceinline__ void stage_chunk(uint32_t sbase, int buf, int kc,
                                            int m0, const __nv_bfloat16* __restrict__ cbb,
                                            int tid)
{
    const int kw = kc * KC;
    const uint32_t ab = sbase + (uint32_t)(buf * STAGE_BYTES);
    const uint32_t bb = ab + A_BYTES;
#pragma unroll
    for (int i = 0; i < 2; ++i) {
        const int idx = tid + 256 * i;
        const int row = idx >> 2, g = idx & 3;
        cp_async16(ab + (uint32_t)(row * ROWB + g * 16),
                   g_Xb + (size_t)(m0 + row) * C_DIM + kw + g * 8);
    }
#pragma unroll
    for (int i = 0; i < 4; ++i) {
        const int idx = tid + 256 * i;
        const int row = idx >> 2, g = idx & 3;
        cp_async16(bb + (uint32_t)(row * ROWB + g * 16),
                   cbb + (size_t)row * C_DIM + kw + g * 8);
    }
}

__global__ __launch_bounds__(256, 1) void gemm_mma_kernel(int q)
{
    extern __shared__ char sm[];
    const uint32_t sbase = smem_u32(sm);
    const __nv_bfloat16* __restrict__ cbb = g_CBb + (size_t)q * K_CODES * C_DIM;

    const int tid  = threadIdx.x;
    const int wid  = tid >> 5;
    const int lane = tid & 31;
    const int wr   = wid & 3;
    const int wc   = wid >> 2;
    const int lg   = lane >> 2;
    const int lt   = lane & 3;
    const int m0   = blockIdx.x * M_TILE;

    const uint32_t aoff0 = (uint32_t)((wr * 32 + (lane & 15)) * ROWB + (lane >> 4) * 16);
    const uint32_t aoff1 = aoff0 + 16 * ROWB;
    const uint32_t boff  = (uint32_t)((wc * 128 + (lane & 7) + ((lane >> 4) << 3)) * ROWB
                                      + (((lane >> 3) & 1) * 16));

    float v[4][4];
    int   ix[4][4];
#pragma unroll
    for (int r = 0; r < 4; ++r)
#pragma unroll
        for (int j = 0; j < 4; ++j) { v[r][j] = 3.4e38f; ix[r][j] = 0; }

    const float* __restrict__ norms = g_norm + q * K_CODES;

    for (int nt = 0; nt < N_PASSES; ++nt) {
        const int n0 = nt * N_TILE;
        const __nv_bfloat16* cbn0 = cbb + (size_t)n0 * C_DIM;

        float acc[2][16][4];
#pragma unroll
        for (int s = 0; s < 2; ++s)
#pragma unroll
            for (int ns = 0; ns < 16; ++ns)
#pragma unroll
                for (int j = 0; j < 4; ++j) acc[s][ns][j] = 0.0f;

        __syncthreads();
        stage_chunk(sbase, 0, 0, m0, cbn0, tid); cp_commit();
        stage_chunk(sbase, 1, 1, m0, cbn0, tid); cp_commit();

#pragma unroll 1
        for (int kc = 0; kc < K_CHUNKS; ++kc) {
            if (kc == K_CHUNKS - 1) cp_wait<0>(); else cp_wait<1>();
            __syncthreads();
            if (kc + 2 < K_CHUNKS) {
                stage_chunk(sbase, (kc + 2) % STAGES, kc + 2, m0, cbn0, tid);
                cp_commit();
            }

            const uint32_t Ab = sbase + (uint32_t)((kc % STAGES) * STAGE_BYTES);
            const uint32_t Bb = Ab + A_BYTES;

#pragma unroll
            for (int ks = 0; ks < 2; ++ks) {
                const uint32_t kb = (uint32_t)(ks * 32);
                uint32_t a[2][4];
                ldsm_x4(a[0][0], a[0][1], a[0][2], a[0][3], Ab + aoff0 + kb);
                ldsm_x4(a[1][0], a[1][1], a[1][2], a[1][3], Ab + aoff1 + kb);
#pragma unroll
                for (int p = 0; p < 8; ++p) {
                    uint32_t b0, b1, b2, b3;
                    ldsm_x4(b0, b1, b2, b3, Bb + boff + (uint32_t)(p * 16 * ROWB) + kb);
                    mma_bf16(acc[0][2 * p    ], a[0], b0, b1);
                    mma_bf16(acc[1][2 * p    ], a[1], b0, b1);
                    mma_bf16(acc[0][2 * p + 1], a[0], b2, b3);
                    mma_bf16(acc[1][2 * p + 1], a[1], b2, b3);
                }
            }
        }

#pragma unroll
        for (int s = 0; s < 2; ++s) {
#pragma unroll
            for (int ns = 0; ns < 16; ++ns) {
                const int n = n0 + wc * 128 + ns * 8 + lt * 2;
                const float nm0 = __ldg(&norms[n]);
                const float nm1 = __ldg(&norms[n + 1]);
                ins4(fmaf(-2.0f, acc[s][ns][0], nm0), n,     v[s*2+0], ix[s*2+0]);
                ins4(fmaf(-2.0f, acc[s][ns][1], nm1), n + 1, v[s*2+0], ix[s*2+0]);
                ins4(fmaf(-2.0f, acc[s][ns][2], nm0), n,     v[s*2+1], ix[s*2+1]);
                ins4(fmaf(-2.0f, acc[s][ns][3], nm1), n + 1, v[s*2+1], ix[s*2+1]);
            }
        }
    }

#pragma unroll
    for (int r = 0; r < 4; ++r) {
#pragma unroll
        for (int o = 1; o <= 2; o <<= 1) {
            float ov[4]; int oi[4];
#pragma unroll
            for (int j = 0; j < 4; ++j) {
                ov[j] = __shfl_xor_sync(0xffffffffu, v[r][j], o);
                oi[j] = __shfl_xor_sync(0xffffffffu, ix[r][j], o);
            }
#pragma unroll
            for (int j = 0; j < 4; ++j) ins4lex(ov[j], oi[j], v[r], ix[r]);
        }
    }

    float* smV = (float*)sm;
    int*   smI = (int*)(sm + 4096);
    __syncthreads();
    if (lt == 0) {
#pragma unroll
        for (int r = 0; r < 4; ++r) {
            const int row = wr * 32 + (r >> 1) * 16 + (r & 1) * 8 + lg;
#pragma unroll
            for (int j = 0; j < 4; ++j) {
                smV[(wc * 128 + row) * 4 + j] = v[r][j];
                smI[(wc * 128 + row) * 4 + j] = ix[r][j];
            }
        }
    }
    __syncthreads();
    if (wid < 4) {
        const int row = wid * 32 + lane;
        float fv[4]; int fi[4];
#pragma unroll
        for (int j = 0; j < 4; ++j) { fv[j] = 3.4e38f; fi[j] = 0x7fffffff; }
#pragma unroll
        for (int h = 0; h < 2; ++h)
#pragma unroll
            for (int j = 0; j < 4; ++j)
                ins4lex(smV[(h * 128 + row) * 4 + j], smI[(h * 128 + row) * 4 + j], fv, fi);
#pragma unroll
        for (int j = 0; j < 4; ++j) g_cand[(m0 + row) * 4 + j] = fi[j];
    }
}

// ---------------------------------------------------------------------------
__global__ __launch_bounds__(128) void fixup_update_kernel(
    const float* __restrict__ cb, int q)
{
    __shared__ float s_d[4][4];
    __shared__ int   s_choice;
    const int m   = blockIdx.x;
    const int tid = threadIdx.x;
    const int wid = tid >> 5;
    const int lid = tid & 31;

    int cand[4];
#pragma unroll
    for (int c = 0; c < 4; ++c) cand[c] = g_cand[m * 4 + c];

    const float4 xr = reinterpret_cast<const float4*>(g_X + (size_t)m * C_DIM)[tid];
    float4 cc[4];
    float  d[4];
#pragma unroll
    for (int c = 0; c < 4; ++c) {
        cc[c] = reinterpret_cast<const float4*>(cb + (size_t)cand[c] * C_DIM)[tid];
        const float dx = xr.x - cc[c].x, dy = xr.y - cc[c].y;
        const float dz = xr.z - cc[c].z, dw = xr.w - cc[c].w;
        d[c] = dx * dx + dy * dy + dz * dz + dw * dw;
    }
#pragma unroll
    for (int c = 0; c < 4; ++c) {
#pragma unroll
        for (int o = 16; o > 0; o >>= 1) d[c] += __shfl_xor_sync(0xffffffffu, d[c], o);
        if (lid == 0) s_d[wid][c] = d[c];
    }
    __syncthreads();
    if (tid == 0) {
        float best = 3.4e38f; int bi = 0x7fffffff, bc = 0;
#pragma unroll
        for (int c = 0; c < 4; ++c) {
            const float dv = s_d[0][c] + s_d[1][c] + s_d[2][c] + s_d[3][c];
            const int   cx = cand[c];
            if (dv < best || (dv == best && cx < bi)) { best = dv; bi = cx; bc = c; }
        }
        s_choice = bc;
        g_idx[q * M_TOT + m] = bi;
        atomicAdd(&g_commit[q], (double)best);
        atomicAdd(&g_hist[bi], 1);
    }
    __syncthreads();
    const int c = s_choice;
    float4 r;
    r.x = xr.x - cc[c].x; r.y = xr.y - cc[c].y;
    r.z = xr.z - cc[c].z; r.w = xr.w - cc[c].w;
    reinterpret_cast<float4*>(g_X + (size_t)m * C_DIM)[tid] = r;

    __nv_bfloat162 h0 = {__float2bfloat16(r.x), __float2bfloat16(r.y)};
    __nv_bfloat162 h1 = {__float2bfloat16(r.z), __float2bfloat16(r.w)};
    __nv_bfloat162* xb = reinterpret_cast<__nv_bfloat162*>(g_Xb + (size_t)m * C_DIM);
    xb[tid * 2]     = h0;
    xb[tid * 2 + 1] = h1;
}

// ---------------------------------------------------------------------------
__global__ void perp_kernel(int q)
{
    __shared__ float red[1024];
    const int k = threadIdx.x;
    const float p = (float)g_hist[k] * (1.0f / (float)M_TOT);
    g_hist[k] = 0;
    red[k] = p * logf(p + 1e-7f);
    __syncthreads();
    for (int off = 512; off > 0; off >>= 1) {
        if (k < off) red[k] += red[k + off];
        __syncthreads();
    }
    if (k == 0) g_perp[q] = expf(-red[0]);
}

// ---------------------------------------------------------------------------
__global__ void qout_kernel(const float* __restrict__ codebooks,
                            float* __restrict__ out)
{
    __shared__ float tile[32][33];
    __shared__ int   sidx[Q_LAYERS][32];
    const int b  = blockIdx.z;
    const int c0 = blockIdx.y * 32;
    const int t0 = blockIdx.x * 32;
    const int tx = threadIdx.x;
    const int ty = threadIdx.y;
    const int tid = ty * 32 + tx;

    if (tid < Q_LAYERS * 32) {
        const int q = tid >> 5, t = tid & 31;
        sidx[q][t] = g_idx[q * M_TOT + b * T_DIM + t0 + t];
    }
    __syncthreads();

#pragma unroll
    for (int i = ty; i < 32; i += 8) {
        float s = 0.0f;
#pragma unroll
        for (int q = 0; q < Q_LAYERS; ++q)
            s += codebooks[((size_t)q * K_CODES + sidx[q][i]) * C_DIM + c0 + tx];
        tile[i][tx] = s;
    }
    __syncthreads();

    float* op = out + (size_t)b * C_DIM * T_DIM;
#pragma unroll
    for (int i = ty; i < 32; i += 8)
        op[(size_t)(c0 + i) * T_DIM + t0 + tx] = tile[tx][i];
}

// ---------------------------------------------------------------------------
__global__ void idx_out_kernel(float* __restrict__ out)
{
    const int i = blockIdx.x * blockDim.x + threadIdx.x;
    if (i >= OUT_IDX_ELEMS) return;
    const int m = i / Q_LAYERS;
    const int q = i - m * Q_LAYERS;
    out[OUT_QOUT_ELEMS + i] = (float)g_idx[q * M_TOT + m];
}

__global__ void scalar_out_kernel(float* __restrict__ out)
{
    if (threadIdx.x == 0) {
        double cs = 0.0;
        float  ps = 0.0f;
        for (int q = 0; q < Q_LAYERS; ++q) {
            cs += g_commit[q] / (double)((double)M_TOT * (double)C_DIM);
            ps += g_perp[q];
        }
        out[OUT_QOUT_ELEMS + OUT_IDX_ELEMS + 0] = (float)(cs / (double)Q_LAYERS);
        out[OUT_QOUT_ELEMS + OUT_IDX_ELEMS + 1] = ps / (float)Q_LAYERS;
    }
}

// ---------------------------------------------------------------------------
extern "C" void kernel_launch(void* const* d_in, const int* in_sizes, int n_in,
                              void* d_out, int out_size)
{
    const float* x         = (const float*)d_in[0];
    const float* codebooks = (const float*)d_in[1];
    float* out = (float*)d_out;
    (void)in_sizes; (void)n_in; (void)out_size;

    static bool attr_set = false;
    if (!attr_set) {
        cudaFuncSetAttribute(gemm_mma_kernel,
                             cudaFuncAttributeMaxDynamicSharedMemorySize, SMEM_BYTES);
        attr_set = true;
    }

    transpose_in_kernel<<<dim3(T_DIM / 32, C_DIM / 32, B_DIM), dim3(32, 8)>>>(x);
    norms_all_kernel<<<Q_LAYERS * K_CODES, 128>>>(codebooks);

    for (int q = 0; q < Q_LAYERS; ++q) {
        const float* cb = codebooks + (size_t)q * K_CODES * C_DIM;
        gemm_mma_kernel<<<M_TOT / M_TILE, 256, SMEM_BYTES>>>(q);
        fixup_update_kernel<<<M_TOT, 128>>>(cb, q);
        perp_kernel<<<1, 1024>>>(q);
    }

    qout_kernel<<<dim3(T_DIM / 32, C_DIM / 32, B_DIM), dim3(32, 8)>>>(codebooks, out);
    idx_out_kernel<<<(OUT_IDX_ELEMS + 255) / 256, 256>>>(out);
    scalar_out_kernel<<<1, 32>>>(out);
}

// round 6
// speedup vs baseline: 5.4457x; 1.0865x over previous
#include <cuda_runtime.h>
#include <cuda_bf16.h>
#include <cstdint>

// ---------------- problem constants ----------------
#define B_DIM    64
#define C_DIM    512
#define T_DIM    256
#define Q_LAYERS 6
#define K_CODES  1024
#define M_TOT    (B_DIM * T_DIM)                    // 16384
#define OUT_QOUT_ELEMS (B_DIM * C_DIM * T_DIM)      // 8388608
#define OUT_IDX_ELEMS  (B_DIM * T_DIM * Q_LAYERS)   // 98304

// ---------------- GEMM tiling (bf16) ----------------
#define M_TILE   128
#define N_TILE   256
#define N_PASSES (K_CODES / N_TILE)  // 4
#define KC       32                  // bf16 k-elems per staged chunk (64B/row)
#define K_CHUNKS (C_DIM / KC)        // 16
#define STAGES   4
#define ROWB     80                  // smem row stride bytes (40 bf16)
#define A_BYTES  (M_TILE * ROWB)     // 10240
#define B_BYTES  (N_TILE * ROWB)     // 20480
#define STAGE_BYTES (A_BYTES + B_BYTES)        // 30720
#define SMEM_BYTES  (STAGES * STAGE_BYTES)     // 122880

// ---------------- device scratch ----------------
__device__ __align__(16) float          g_X [M_TOT * C_DIM];
__device__ __align__(16) __nv_bfloat16  g_Xb[M_TOT * C_DIM];
__device__ __align__(16) __nv_bfloat16  g_CBb[Q_LAYERS * K_CODES * C_DIM];
__device__ int    g_idx[Q_LAYERS * M_TOT];
__device__ float  g_norm[Q_LAYERS * K_CODES];
__device__ int    g_hist[Q_LAYERS * K_CODES];
__device__ double g_commit[Q_LAYERS];
__device__ float  g_perp[Q_LAYERS];

// ---------------- helpers ----------------
__device__ __forceinline__ uint32_t smem_u32(const void* p) {
    uint32_t a;
    asm("{ .reg .u64 t; cvta.to.shared.u64 t, %1; cvt.u32.u64 %0, t; }" : "=r"(a) : "l"(p));
    return a;
}
__device__ __forceinline__ void cp_async16(uint32_t dst, const void* src) {
    asm volatile("cp.async.cg.shared.global [%0], [%1], 16;" :: "r"(dst), "l"(src));
}
__device__ __forceinline__ void cp_commit() {
    asm volatile("cp.async.commit_group;" ::: "memory");
}
template <int N> __device__ __forceinline__ void cp_wait() {
    asm volatile("cp.async.wait_group %0;" :: "n"(N) : "memory");
}
__device__ __forceinline__ void ldsm_x4(uint32_t& r0, uint32_t& r1,
                                        uint32_t& r2, uint32_t& r3, uint32_t addr) {
    asm volatile("ldmatrix.sync.aligned.m8n8.x4.shared.b16 {%0,%1,%2,%3}, [%4];"
                 : "=r"(r0), "=r"(r1), "=r"(r2), "=r"(r3) : "r"(addr));
}
__device__ __forceinline__ void mma_bf16(float* c, const uint32_t* a,
                                         uint32_t b0, uint32_t b1) {
    asm volatile(
        "mma.sync.aligned.m16n8k16.row.col.f32.bf16.bf16.f32 "
        "{%0,%1,%2,%3}, {%4,%5,%6,%7}, {%8,%9}, {%0,%1,%2,%3};"
        : "+f"(c[0]), "+f"(c[1]), "+f"(c[2]), "+f"(c[3])
        : "r"(a[0]), "r"(a[1]), "r"(a[2]), "r"(a[3]), "r"(b0), "r"(b1));
}

__device__ __forceinline__ void ins4(float s, int n, float v[4], int ix[4]) {
    if (s < v[3]) {
        if (s < v[1]) {
            if (s < v[0]) { v[3]=v[2];ix[3]=ix[2]; v[2]=v[1];ix[2]=ix[1];
                            v[1]=v[0];ix[1]=ix[0]; v[0]=s;ix[0]=n; }
            else          { v[3]=v[2];ix[3]=ix[2]; v[2]=v[1];ix[2]=ix[1];
                            v[1]=s;ix[1]=n; }
        } else {
            if (s < v[2]) { v[3]=v[2];ix[3]=ix[2]; v[2]=s;ix[2]=n; }
            else          { v[3]=s;ix[3]=n; }
        }
    }
}
__device__ __forceinline__ bool lexlt(float s, int n, float v, int i) {
    return (s < v) || (s == v && n < i);
}
__device__ __forceinline__ void ins4lex(float s, int n, float v[4], int ix[4]) {
    if (lexlt(s, n, v[3], ix[3])) {
        if (lexlt(s, n, v[1], ix[1])) {
            if (lexlt(s, n, v[0], ix[0])) { v[3]=v[2];ix[3]=ix[2]; v[2]=v[1];ix[2]=ix[1];
                                            v[1]=v[0];ix[1]=ix[0]; v[0]=s;ix[0]=n; }
            else                          { v[3]=v[2];ix[3]=ix[2]; v[2]=v[1];ix[2]=ix[1];
                                            v[1]=s;ix[1]=n; }
        } else {
            if (lexlt(s, n, v[2], ix[2])) { v[3]=v[2];ix[3]=ix[2]; v[2]=s;ix[2]=n; }
            else                          { v[3]=s;ix[3]=n; }
        }
    }
}

// ---------------------------------------------------------------------------
// 1) Transpose x (B,C,T) -> g_X fp32 + g_Xb bf16  (B*T, C)
// ---------------------------------------------------------------------------
__global__ void transpose_in_kernel(const float* __restrict__ x)
{
    __shared__ float tile[32][33];
    const int b  = blockIdx.z;
    const int c0 = blockIdx.y * 32;
    const int t0 = blockIdx.x * 32;
    const int tx = threadIdx.x;
    const int ty = threadIdx.y;

    const float* xp = x + (size_t)b * C_DIM * T_DIM;
#pragma unroll
    for (int i = ty; i < 32; i += 8)
        tile[i][tx] = xp[(size_t)(c0 + i) * T_DIM + t0 + tx];
    __syncthreads();
#pragma unroll
    for (int i = ty; i < 32; i += 8) {
        const float vv = tile[tx][i];
        const size_t o = (size_t)(b * T_DIM + t0 + i) * C_DIM + c0 + tx;
        g_X[o]  = vv;
        g_Xb[o] = __float2bfloat16(vv);
    }
}

// ---------------------------------------------------------------------------
// 2) Code norms + bf16 codebook conversion + zero commit accumulators
// ---------------------------------------------------------------------------
__global__ void norms_all_kernel(const float* __restrict__ codebooks)
{
    __shared__ float red[128];
    const int gk  = blockIdx.x;
    const int tid = threadIdx.x;
    const float4 c = reinterpret_cast<const float4*>(codebooks + (size_t)gk * C_DIM)[tid];
    red[tid] = c.x * c.x + c.y * c.y + c.z * c.z + c.w * c.w;

    __nv_bfloat162 h0 = {__float2bfloat16(c.x), __float2bfloat16(c.y)};
    __nv_bfloat162 h1 = {__float2bfloat16(c.z), __float2bfloat16(c.w)};
    __nv_bfloat162* dst = reinterpret_cast<__nv_bfloat162*>(g_CBb + (size_t)gk * C_DIM);
    dst[tid * 2]     = h0;
    dst[tid * 2 + 1] = h1;

    __syncthreads();
    for (int off = 64; off > 0; off >>= 1) {
        if (tid < off) red[tid] += red[tid + off];
        __syncthreads();
    }
    if (tid == 0) {
        g_norm[gk] = red[0];
        if (gk < Q_LAYERS) g_commit[gk] = 0.0;
    }
}

// ---------------------------------------------------------------------------
// 3) Fused: bf16 mma GEMM + top-4 candidates + exact fp32 re-rank +
//    residual update + stats.  grid = 128 CTAs, block = 256 threads.
// ---------------------------------------------------------------------------
__device__ __forceinline__ void stage_chunk(uint32_t sbase, int buf, int kc,
                                            int m0, const __nv_bfloat16* __restrict__ cbb,
                                            int tid)
{
    const int kw = kc * KC;
    const uint32_t ab = sbase + (uint32_t)(buf * STAGE_BYTES);
    const uint32_t bb = ab + A_BYTES;
#pragma unroll
    for (int i = 0; i < 2; ++i) {
        const int idx = tid + 256 * i;
        const int row = idx >> 2, g = idx & 3;
        cp_async16(ab + (uint32_t)(row * ROWB + g * 16),
                   g_Xb + (size_t)(m0 + row) * C_DIM + kw + g * 8);
    }
#pragma unroll
    for (int i = 0; i < 4; ++i) {
        const int idx = tid + 256 * i;
        const int row = idx >> 2, g = idx & 3;
        cp_async16(bb + (uint32_t)(row * ROWB + g * 16),
                   cbb + (size_t)row * C_DIM + kw + g * 8);
    }
}

__global__ __launch_bounds__(256, 1) void gemm_fused_kernel(
    const float* __restrict__ cbf, int q)
{
    extern __shared__ char sm[];
    const uint32_t sbase = smem_u32(sm);
    const __nv_bfloat16* __restrict__ cbb = g_CBb + (size_t)q * K_CODES * C_DIM;

    const int tid  = threadIdx.x;
    const int wid  = tid >> 5;
    const int lane = tid & 31;
    const int wr   = wid & 3;
    const int wc   = wid >> 2;
    const int lg   = lane >> 2;
    const int lt   = lane & 3;
    const int m0   = blockIdx.x * M_TILE;

    const uint32_t aoff0 = (uint32_t)((wr * 32 + (lane & 15)) * ROWB + (lane >> 4) * 16);
    const uint32_t aoff1 = aoff0 + 16 * ROWB;
    const uint32_t boff  = (uint32_t)((wc * 128 + (lane & 7) + ((lane >> 4) << 3)) * ROWB
                                      + (((lane >> 3) & 1) * 16));

    float v[4][4];
    int   ix[4][4];
#pragma unroll
    for (int r = 0; r < 4; ++r)
#pragma unroll
        for (int j = 0; j < 4; ++j) { v[r][j] = 3.4e38f; ix[r][j] = 0; }

    const float* __restrict__ norms = g_norm + q * K_CODES;

    for (int nt = 0; nt < N_PASSES; ++nt) {
        const int n0 = nt * N_TILE;
        const __nv_bfloat16* cbn0 = cbb + (size_t)n0 * C_DIM;

        float acc[2][16][4];
#pragma unroll
        for (int s = 0; s < 2; ++s)
#pragma unroll
            for (int ns = 0; ns < 16; ++ns)
#pragma unroll
                for (int j = 0; j < 4; ++j) acc[s][ns][j] = 0.0f;

        __syncthreads();                        // stage bufs free (prev pass done)
        stage_chunk(sbase, 0, 0, m0, cbn0, tid); cp_commit();
        stage_chunk(sbase, 1, 1, m0, cbn0, tid); cp_commit();
        stage_chunk(sbase, 2, 2, m0, cbn0, tid); cp_commit();

#pragma unroll 1
        for (int kc = 0; kc < K_CHUNKS; ++kc) {
            if (kc < K_CHUNKS - 2)      cp_wait<2>();
            else if (kc == K_CHUNKS - 2) cp_wait<1>();
            else                         cp_wait<0>();
            __syncthreads();                    // chunk kc visible
            if (kc + 3 < K_CHUNKS) {
                stage_chunk(sbase, (kc + 3) % STAGES, kc + 3, m0, cbn0, tid);
                cp_commit();
            }

            const uint32_t Ab = sbase + (uint32_t)((kc % STAGES) * STAGE_BYTES);
            const uint32_t Bb = Ab + A_BYTES;

#pragma unroll
            for (int ks = 0; ks < 2; ++ks) {
                const uint32_t kb = (uint32_t)(ks * 32);
                uint32_t a[2][4];
                ldsm_x4(a[0][0], a[0][1], a[0][2], a[0][3], Ab + aoff0 + kb);
                ldsm_x4(a[1][0], a[1][1], a[1][2], a[1][3], Ab + aoff1 + kb);
#pragma unroll
                for (int p = 0; p < 8; ++p) {
                    uint32_t b0, b1, b2, b3;
                    ldsm_x4(b0, b1, b2, b3, Bb + boff + (uint32_t)(p * 16 * ROWB) + kb);
                    mma_bf16(acc[0][2 * p    ], a[0], b0, b1);
                    mma_bf16(acc[1][2 * p    ], a[1], b0, b1);
                    mma_bf16(acc[0][2 * p + 1], a[0], b2, b3);
                    mma_bf16(acc[1][2 * p + 1], a[1], b2, b3);
                }
            }
        }

#pragma unroll
        for (int s = 0; s < 2; ++s) {
#pragma unroll
            for (int ns = 0; ns < 16; ++ns) {
                const int n = n0 + wc * 128 + ns * 8 + lt * 2;
                const float nm0 = __ldg(&norms[n]);
                const float nm1 = __ldg(&norms[n + 1]);
                ins4(fmaf(-2.0f, acc[s][ns][0], nm0), n,     v[s*2+0], ix[s*2+0]);
                ins4(fmaf(-2.0f, acc[s][ns][1], nm1), n + 1, v[s*2+0], ix[s*2+0]);
                ins4(fmaf(-2.0f, acc[s][ns][2], nm0), n,     v[s*2+1], ix[s*2+1]);
                ins4(fmaf(-2.0f, acc[s][ns][3], nm1), n + 1, v[s*2+1], ix[s*2+1]);
            }
        }
    }

    // merge across lt (4 lanes per row)
#pragma unroll
    for (int r = 0; r < 4; ++r) {
#pragma unroll
        for (int o = 1; o <= 2; o <<= 1) {
            float ov[4]; int oi[4];
#pragma unroll
            for (int j = 0; j < 4; ++j) {
                ov[j] = __shfl_xor_sync(0xffffffffu, v[r][j], o);
                oi[j] = __shfl_xor_sync(0xffffffffu, ix[r][j], o);
            }
#pragma unroll
            for (int j = 0; j < 4; ++j) ins4lex(ov[j], oi[j], v[r], ix[r]);
        }
    }

    // cross-warp merge (wc=0 vs wc=1) into final candidate table sFi[128][4]
    float* smV = (float*)sm;                 // [2][128][4] floats @0
    int*   smI = (int*)(sm + 4096);          // [2][128][4] ints   @4096
    int*   sFi = (int*)(sm + 8192);          // [128][4] final     @8192
    float* sCm = (float*)(sm + 10240);       // [8] per-warp commit @10240
    __syncthreads();
    if (lt == 0) {
#pragma unroll
        for (int r = 0; r < 4; ++r) {
            const int row = wr * 32 + (r >> 1) * 16 + (r & 1) * 8 + lg;
#pragma unroll
            for (int j = 0; j < 4; ++j) {
                smV[(wc * 128 + row) * 4 + j] = v[r][j];
                smI[(wc * 128 + row) * 4 + j] = ix[r][j];
            }
        }
    }
    __syncthreads();
    if (wid < 4) {
        const int row = wid * 32 + lane;
        float fv[4]; int fi[4];
#pragma unroll
        for (int j = 0; j < 4; ++j) { fv[j] = 3.4e38f; fi[j] = 0x7fffffff; }
#pragma unroll
        for (int h = 0; h < 2; ++h)
#pragma unroll
            for (int j = 0; j < 4; ++j)
                ins4lex(smV[(h * 128 + row) * 4 + j], smI[(h * 128 + row) * 4 + j], fv, fi);
#pragma unroll
        for (int j = 0; j < 4; ++j) sFi[row * 4 + j] = fi[j];
    }
    __syncthreads();

    // ---------------- fused exact fp32 fixup + residual update ----------------
    float warp_commit = 0.0f;
    int* hist_q = g_hist + q * K_CODES;

#pragma unroll 1
    for (int i = 0; i < 16; ++i) {
        const int row = wid * 16 + i;
        const int m   = m0 + row;
        int cand[4];
#pragma unroll
        for (int c = 0; c < 4; ++c) cand[c] = sFi[row * 4 + c];

        const float4* xp = reinterpret_cast<const float4*>(g_X + (size_t)m * C_DIM);
        float4 xv[4];
#pragma unroll
        for (int j = 0; j < 4; ++j) xv[j] = xp[lane + 32 * j];

        float d[4];
#pragma unroll
        for (int c = 0; c < 4; ++c) {
            const float4* cp = reinterpret_cast<const float4*>(cbf + (size_t)cand[c] * C_DIM);
            float s = 0.0f;
#pragma unroll
            for (int j = 0; j < 4; ++j) {
                const float4 cv = cp[lane + 32 * j];
                const float dx = xv[j].x - cv.x, dy = xv[j].y - cv.y;
                const float dz = xv[j].z - cv.z, dw = xv[j].w - cv.w;
                s += dx * dx + dy * dy + dz * dz + dw * dw;
            }
            d[c] = s;
        }
#pragma unroll
        for (int c = 0; c < 4; ++c)
#pragma unroll
            for (int o = 16; o > 0; o >>= 1)
                d[c] += __shfl_xor_sync(0xffffffffu, d[c], o);

        float best = d[0]; int bi = cand[0], bc = 0;
#pragma unroll
        for (int c = 1; c < 4; ++c) {
            if (d[c] < best || (d[c] == best && cand[c] < bi)) {
                best = d[c]; bi = cand[c]; bc = c;
            }
        }

        const float4* bp = reinterpret_cast<const float4*>(cbf + (size_t)bi * C_DIM);
        float4* xo = reinterpret_cast<float4*>(g_X + (size_t)m * C_DIM);
        uint2*  xb = reinterpret_cast<uint2*>(g_Xb + (size_t)m * C_DIM);
#pragma unroll
        for (int j = 0; j < 4; ++j) {
            const float4 cv = bp[lane + 32 * j];
            float4 r;
            r.x = xv[j].x - cv.x; r.y = xv[j].y - cv.y;
            r.z = xv[j].z - cv.z; r.w = xv[j].w - cv.w;
            xo[lane + 32 * j] = r;
            __nv_bfloat162 h0 = {__float2bfloat16(r.x), __float2bfloat16(r.y)};
            __nv_bfloat162 h1 = {__float2bfloat16(r.z), __float2bfloat16(r.w)};
            uint2 pk;
            pk.x = *reinterpret_cast<uint32_t*>(&h0);
            pk.y = *reinterpret_cast<uint32_t*>(&h1);
            xb[lane + 32 * j] = pk;
        }

        if (lane == 0) {
            warp_commit += best;
            g_idx[q * M_TOT + m] = bi;
            atomicAdd(&hist_q[bi], 1);
        }
        (void)bc;
    }

    if (lane == 0) sCm[wid] = warp_commit;
    __syncthreads();
    if (tid == 0) {
        float cs = 0.0f;
#pragma unroll
        for (int w = 0; w < 8; ++w) cs += sCm[w];
        atomicAdd(&g_commit[q], (double)cs);
    }
}

// ---------------------------------------------------------------------------
// 4) Perplexity for all layers (one kernel, 6 blocks); re-zeroes histograms
// ---------------------------------------------------------------------------
__global__ void perp_all_kernel()
{
    __shared__ float red[1024];
    const int q = blockIdx.x;
    const int k = threadIdx.x;
    const float p = (float)g_hist[q * K_CODES + k] * (1.0f / (float)M_TOT);
    g_hist[q * K_CODES + k] = 0;
    red[k] = p * logf(p + 1e-7f);
    __syncthreads();
    for (int off = 512; off > 0; off >>= 1) {
        if (k < off) red[k] += red[k + off];
        __syncthreads();
    }
    if (k == 0) g_perp[q] = expf(-red[0]);
}

// ---------------------------------------------------------------------------
// 5) quantized_out: gather-sum 6 codes per (b,t), write transposed (B,C,T)
// ---------------------------------------------------------------------------
__global__ void qout_kernel(const float* __restrict__ codebooks,
                            float* __restrict__ out)
{
    __shared__ float tile[32][33];
    __shared__ int   sidx[Q_LAYERS][32];
    const int b  = blockIdx.z;
    const int c0 = blockIdx.y * 32;
    const int t0 = blockIdx.x * 32;
    const int tx = threadIdx.x;
    const int ty = threadIdx.y;
    const int tid = ty * 32 + tx;

    if (tid < Q_LAYERS * 32) {
        const int q = tid >> 5, t = tid & 31;
        sidx[q][t] = g_idx[q * M_TOT + b * T_DIM + t0 + t];
    }
    __syncthreads();

#pragma unroll
    for (int i = ty; i < 32; i += 8) {
        float s = 0.0f;
#pragma unroll
        for (int q = 0; q < Q_LAYERS; ++q)
            s += codebooks[((size_t)q * K_CODES + sidx[q][i]) * C_DIM + c0 + tx];
        tile[i][tx] = s;
    }
    __syncthreads();

    float* op = out + (size_t)b * C_DIM * T_DIM;
#pragma unroll
    for (int i = ty; i < 32; i += 8)
        op[(size_t)(c0 + i) * T_DIM + t0 + tx] = tile[tx][i];
}

// ---------------------------------------------------------------------------
// 6) Index output (B,T,Q) as float, and scalar losses
// ---------------------------------------------------------------------------
__global__ void idx_out_kernel(float* __restrict__ out)
{
    const int i = blockIdx.x * blockDim.x + threadIdx.x;
    if (i >= OUT_IDX_ELEMS) return;
    const int m = i / Q_LAYERS;
    const int q = i - m * Q_LAYERS;
    out[OUT_QOUT_ELEMS + i] = (float)g_idx[q * M_TOT + m];
}

__global__ void scalar_out_kernel(float* __restrict__ out)
{
    if (threadIdx.x == 0) {
        double cs = 0.0;
        float  ps = 0.0f;
        for (int q = 0; q < Q_LAYERS; ++q) {
            cs += g_commit[q] / (double)((double)M_TOT * (double)C_DIM);
            ps += g_perp[q];
        }
        out[OUT_QOUT_ELEMS + OUT_IDX_ELEMS + 0] = (float)(cs / (double)Q_LAYERS);
        out[OUT_QOUT_ELEMS + OUT_IDX_ELEMS + 1] = ps / (float)Q_LAYERS;
    }
}

// ---------------------------------------------------------------------------
extern "C" void kernel_launch(void* const* d_in, const int* in_sizes, int n_in,
                              void* d_out, int out_size)
{
    const float* x         = (const float*)d_in[0];
    const float* codebooks = (const float*)d_in[1];
    float* out = (float*)d_out;
    (void)in_sizes; (void)n_in; (void)out_size;

    static bool attr_set = false;
    if (!attr_set) {
        cudaFuncSetAttribute(gemm_fused_kernel,
                             cudaFuncAttributeMaxDynamicSharedMemorySize, SMEM_BYTES);
        attr_set = true;
    }

    transpose_in_kernel<<<dim3(T_DIM / 32, C_DIM / 32, B_DIM), dim3(32, 8)>>>(x);
    norms_all_kernel<<<Q_LAYERS * K_CODES, 128>>>(codebooks);

    for (int q = 0; q < Q_LAYERS; ++q) {
        const float* cb = codebooks + (size_t)q * K_CODES * C_DIM;
        gemm_fused_kernel<<<M_TOT / M_TILE, 256, SMEM_BYTES>>>(cb, q);
    }

    perp_all_kernel<<<Q_LAYERS, 1024>>>();
    qout_kernel<<<dim3(T_DIM / 32, C_DIM / 32, B_DIM), dim3(32, 8)>>>(codebooks, out);
    idx_out_kernel<<<(OUT_IDX_ELEMS + 255) / 256, 256>>>(out);
    scalar_out_kernel<<<1, 32>>>(out);
}

// round 7
// speedup vs baseline: 6.1888x; 1.1364x over previous
#include <cuda_runtime.h>
#include <cuda_bf16.h>
#include <cstdint>

// ---------------- problem constants ----------------
#define B_DIM    64
#define C_DIM    512
#define T_DIM    256
#define Q_LAYERS 6
#define K_CODES  1024
#define M_TOT    (B_DIM * T_DIM)                    // 16384
#define OUT_QOUT_ELEMS (B_DIM * C_DIM * T_DIM)      // 8388608
#define OUT_IDX_ELEMS  (B_DIM * T_DIM * Q_LAYERS)   // 98304

// ---------------- GEMM tiling (bf16) ----------------
#define M_TILE   64                  // rows per CTA (halved for 2 CTA/SM)
#define N_TILE   256
#define N_PASSES (K_CODES / N_TILE)  // 4
#define KC       32                  // bf16 k-elems per staged chunk (64B/row)
#define K_CHUNKS (C_DIM / KC)        // 16
#define STAGES   3
#define ROWB     80                  // smem row stride bytes (40 bf16)
#define A_BYTES  (M_TILE * ROWB)     // 5120
#define B_BYTES  (N_TILE * ROWB)     // 20480
#define STAGE_BYTES (A_BYTES + B_BYTES)        // 25600
#define SMEM_BYTES  (STAGES * STAGE_BYTES)     // 76800

// ---------------- device scratch ----------------
__device__ __align__(16) float          g_X [M_TOT * C_DIM];
__device__ __align__(16) __nv_bfloat16  g_Xb[M_TOT * C_DIM];
__device__ __align__(16) __nv_bfloat16  g_CBb[Q_LAYERS * K_CODES * C_DIM];
__device__ int    g_idx[Q_LAYERS * M_TOT];
__device__ float  g_norm[Q_LAYERS * K_CODES];
__device__ int    g_hist[Q_LAYERS * K_CODES];
__device__ double g_commit[Q_LAYERS];
__device__ float  g_perp[Q_LAYERS];

// ---------------- helpers ----------------
__device__ __forceinline__ uint32_t smem_u32(const void* p) {
    uint32_t a;
    asm("{ .reg .u64 t; cvta.to.shared.u64 t, %1; cvt.u32.u64 %0, t; }" : "=r"(a) : "l"(p));
    return a;
}
__device__ __forceinline__ void cp_async16(uint32_t dst, const void* src) {
    asm volatile("cp.async.cg.shared.global [%0], [%1], 16;" :: "r"(dst), "l"(src));
}
__device__ __forceinline__ void cp_commit() {
    asm volatile("cp.async.commit_group;" ::: "memory");
}
template <int N> __device__ __forceinline__ void cp_wait() {
    asm volatile("cp.async.wait_group %0;" :: "n"(N) : "memory");
}
__device__ __forceinline__ void ldsm_x4(uint32_t& r0, uint32_t& r1,
                                        uint32_t& r2, uint32_t& r3, uint32_t addr) {
    asm volatile("ldmatrix.sync.aligned.m8n8.x4.shared.b16 {%0,%1,%2,%3}, [%4];"
                 : "=r"(r0), "=r"(r1), "=r"(r2), "=r"(r3) : "r"(addr));
}
__device__ __forceinline__ void mma_bf16(float* c, const uint32_t* a,
                                         uint32_t b0, uint32_t b1) {
    asm volatile(
        "mma.sync.aligned.m16n8k16.row.col.f32.bf16.bf16.f32 "
        "{%0,%1,%2,%3}, {%4,%5,%6,%7}, {%8,%9}, {%0,%1,%2,%3};"
        : "+f"(c[0]), "+f"(c[1]), "+f"(c[2]), "+f"(c[3])
        : "r"(a[0]), "r"(a[1]), "r"(a[2]), "r"(a[3]), "r"(b0), "r"(b1));
}

__device__ __forceinline__ void ins4(float s, int n, float v[4], int ix[4]) {
    if (s < v[3]) {
        if (s < v[1]) {
            if (s < v[0]) { v[3]=v[2];ix[3]=ix[2]; v[2]=v[1];ix[2]=ix[1];
                            v[1]=v[0];ix[1]=ix[0]; v[0]=s;ix[0]=n; }
            else          { v[3]=v[2];ix[3]=ix[2]; v[2]=v[1];ix[2]=ix[1];
                            v[1]=s;ix[1]=n; }
        } else {
            if (s < v[2]) { v[3]=v[2];ix[3]=ix[2]; v[2]=s;ix[2]=n; }
            else          { v[3]=s;ix[3]=n; }
        }
    }
}
__device__ __forceinline__ bool lexlt(float s, int n, float v, int i) {
    return (s < v) || (s == v && n < i);
}
__device__ __forceinline__ void ins4lex(float s, int n, float v[4], int ix[4]) {
    if (lexlt(s, n, v[3], ix[3])) {
        if (lexlt(s, n, v[1], ix[1])) {
            if (lexlt(s, n, v[0], ix[0])) { v[3]=v[2];ix[3]=ix[2]; v[2]=v[1];ix[2]=ix[1];
                                            v[1]=v[0];ix[1]=ix[0]; v[0]=s;ix[0]=n; }
            else                          { v[3]=v[2];ix[3]=ix[2]; v[2]=v[1];ix[2]=ix[1];
                                            v[1]=s;ix[1]=n; }
        } else {
            if (lexlt(s, n, v[2], ix[2])) { v[3]=v[2];ix[3]=ix[2]; v[2]=s;ix[2]=n; }
            else                          { v[3]=s;ix[3]=n; }
        }
    }
}

// ---------------------------------------------------------------------------
// 1) Transpose x (B,C,T) -> g_X fp32 + g_Xb bf16  (B*T, C)
// ---------------------------------------------------------------------------
__global__ void transpose_in_kernel(const float* __restrict__ x)
{
    __shared__ float tile[32][33];
    const int b  = blockIdx.z;
    const int c0 = blockIdx.y * 32;
    const int t0 = blockIdx.x * 32;
    const int tx = threadIdx.x;
    const int ty = threadIdx.y;

    const float* xp = x + (size_t)b * C_DIM * T_DIM;
#pragma unroll
    for (int i = ty; i < 32; i += 8)
        tile[i][tx] = xp[(size_t)(c0 + i) * T_DIM + t0 + tx];
    __syncthreads();
#pragma unroll
    for (int i = ty; i < 32; i += 8) {
        const float vv = tile[tx][i];
        const size_t o = (size_t)(b * T_DIM + t0 + i) * C_DIM + c0 + tx;
        g_X[o]  = vv;
        g_Xb[o] = __float2bfloat16(vv);
    }
}

// ---------------------------------------------------------------------------
// 2) Code norms + bf16 codebook conversion + zero commit accumulators
// ---------------------------------------------------------------------------
__global__ void norms_all_kernel(const float* __restrict__ codebooks)
{
    __shared__ float red[128];
    const int gk  = blockIdx.x;
    const int tid = threadIdx.x;
    const float4 c = reinterpret_cast<const float4*>(codebooks + (size_t)gk * C_DIM)[tid];
    red[tid] = c.x * c.x + c.y * c.y + c.z * c.z + c.w * c.w;

    __nv_bfloat162 h0 = {__float2bfloat16(c.x), __float2bfloat16(c.y)};
    __nv_bfloat162 h1 = {__float2bfloat16(c.z), __float2bfloat16(c.w)};
    __nv_bfloat162* dst = reinterpret_cast<__nv_bfloat162*>(g_CBb + (size_t)gk * C_DIM);
    dst[tid * 2]     = h0;
    dst[tid * 2 + 1] = h1;

    __syncthreads();
    for (int off = 64; off > 0; off >>= 1) {
        if (tid < off) red[tid] += red[tid + off];
        __syncthreads();
    }
    if (tid == 0) {
        g_norm[gk] = red[0];
        if (gk < Q_LAYERS) g_commit[gk] = 0.0;
    }
}

// ---------------------------------------------------------------------------
// 3) Fused: bf16 mma GEMM + top-4 + exact fp32 re-rank + residual update.
//    grid = 256 CTAs (64 rows each), block = 256 threads, 2 CTAs/SM.
//    Warp layout: wr = wid&1 (row group of 32), wc = wid>>1 (64-code group).
// ---------------------------------------------------------------------------
__device__ __forceinline__ void stage_chunk(uint32_t sbase, int buf, int kc,
                                            int m0, const __nv_bfloat16* __restrict__ cbb,
                                            int tid)
{
    const int kw = kc * KC;
    const uint32_t ab = sbase + (uint32_t)(buf * STAGE_BYTES);
    const uint32_t bb = ab + A_BYTES;
    // A: 64 rows x 4 x 16B = 256 units (1 per thread)
    {
        const int row = tid >> 2, g = tid & 3;
        cp_async16(ab + (uint32_t)(row * ROWB + g * 16),
                   g_Xb + (size_t)(m0 + row) * C_DIM + kw + g * 8);
    }
    // B: 256 rows x 4 x 16B = 1024 units (4 per thread)
#pragma unroll
    for (int i = 0; i < 4; ++i) {
        const int idx = tid + 256 * i;
        const int row = idx >> 2, g = idx & 3;
        cp_async16(bb + (uint32_t)(row * ROWB + g * 16),
                   cbb + (size_t)row * C_DIM + kw + g * 8);
    }
}

__global__ __launch_bounds__(256, 2) void gemm_fused_kernel(
    const float* __restrict__ cbf, int q)
{
    extern __shared__ char sm[];
    const uint32_t sbase = smem_u32(sm);
    const __nv_bfloat16* __restrict__ cbb = g_CBb + (size_t)q * K_CODES * C_DIM;

    const int tid  = threadIdx.x;
    const int wid  = tid >> 5;
    const int lane = tid & 31;
    const int wr   = wid & 1;        // row group (32 rows)
    const int wc   = wid >> 1;       // code group (64 codes within pass)
    const int lg   = lane >> 2;
    const int lt   = lane & 3;
    const int m0   = blockIdx.x * M_TILE;

    const uint32_t aoff0 = (uint32_t)((wr * 32 + (lane & 15)) * ROWB + (lane >> 4) * 16);
    const uint32_t aoff1 = aoff0 + 16 * ROWB;
    const uint32_t boff  = (uint32_t)((wc * 64 + (lane & 7) + ((lane >> 4) << 3)) * ROWB
                                      + (((lane >> 3) & 1) * 16));

    float v[4][4];
    int   ix[4][4];
#pragma unroll
    for (int r = 0; r < 4; ++r)
#pragma unroll
        for (int j = 0; j < 4; ++j) { v[r][j] = 3.4e38f; ix[r][j] = 0; }

    const float* __restrict__ norms = g_norm + q * K_CODES;

    for (int nt = 0; nt < N_PASSES; ++nt) {
        const int n0 = nt * N_TILE;
        const __nv_bfloat16* cbn0 = cbb + (size_t)n0 * C_DIM;

        float acc[2][8][4];
#pragma unroll
        for (int s = 0; s < 2; ++s)
#pragma unroll
            for (int ns = 0; ns < 8; ++ns)
#pragma unroll
                for (int j = 0; j < 4; ++j) acc[s][ns][j] = 0.0f;

        __syncthreads();                        // stage bufs free (prev pass done)
        stage_chunk(sbase, 0, 0, m0, cbn0, tid); cp_commit();
        stage_chunk(sbase, 1, 1, m0, cbn0, tid); cp_commit();

#pragma unroll 1
        for (int kc = 0; kc < K_CHUNKS; ++kc) {
            if (kc == K_CHUNKS - 1) cp_wait<0>(); else cp_wait<1>();
            __syncthreads();                    // chunk kc visible
            if (kc + 2 < K_CHUNKS) {
                stage_chunk(sbase, (kc + 2) % STAGES, kc + 2, m0, cbn0, tid);
                cp_commit();
            }

            const uint32_t Ab = sbase + (uint32_t)((kc % STAGES) * STAGE_BYTES);
            const uint32_t Bb = Ab + A_BYTES;

#pragma unroll
            for (int ks = 0; ks < 2; ++ks) {
                const uint32_t kb = (uint32_t)(ks * 32);
                uint32_t a[2][4];
                ldsm_x4(a[0][0], a[0][1], a[0][2], a[0][3], Ab + aoff0 + kb);
                ldsm_x4(a[1][0], a[1][1], a[1][2], a[1][3], Ab + aoff1 + kb);
#pragma unroll
                for (int p = 0; p < 4; ++p) {
                    uint32_t b0, b1, b2, b3;
                    ldsm_x4(b0, b1, b2, b3, Bb + boff + (uint32_t)(p * 16 * ROWB) + kb);
                    mma_bf16(acc[0][2 * p    ], a[0], b0, b1);
                    mma_bf16(acc[1][2 * p    ], a[1], b0, b1);
                    mma_bf16(acc[0][2 * p + 1], a[0], b2, b3);
                    mma_bf16(acc[1][2 * p + 1], a[1], b2, b3);
                }
            }
        }

        // epilogue: score = ||cb||^2 - 2*dot; per-thread top-4 per row-slot
#pragma unroll
        for (int s = 0; s < 2; ++s) {
#pragma unroll
            for (int ns = 0; ns < 8; ++ns) {
                const int n = n0 + wc * 64 + ns * 8 + lt * 2;
                const float nm0 = __ldg(&norms[n]);
                const float nm1 = __ldg(&norms[n + 1]);
                ins4(fmaf(-2.0f, acc[s][ns][0], nm0), n,     v[s*2+0], ix[s*2+0]);
                ins4(fmaf(-2.0f, acc[s][ns][1], nm1), n + 1, v[s*2+0], ix[s*2+0]);
                ins4(fmaf(-2.0f, acc[s][ns][2], nm0), n,     v[s*2+1], ix[s*2+1]);
                ins4(fmaf(-2.0f, acc[s][ns][3], nm1), n + 1, v[s*2+1], ix[s*2+1]);
            }
        }
    }

    // merge across lt (4 lanes per row)
#pragma unroll
    for (int r = 0; r < 4; ++r) {
#pragma unroll
        for (int o = 1; o <= 2; o <<= 1) {
            float ov[4]; int oi[4];
#pragma unroll
            for (int j = 0; j < 4; ++j) {
                ov[j] = __shfl_xor_sync(0xffffffffu, v[r][j], o);
                oi[j] = __shfl_xor_sync(0xffffffffu, ix[r][j], o);
            }
#pragma unroll
            for (int j = 0; j < 4; ++j) ins4lex(ov[j], oi[j], v[r], ix[r]);
        }
    }

    // cross-warp merge (4 wc groups) into final candidate table sFi[64][4]
    float* smV = (float*)sm;                 // [4][64][4] floats @0     (4096 B)
    int*   smI = (int*)(sm + 4096);          // [4][64][4] ints   @4096  (4096 B)
    int*   sFi = (int*)(sm + 8192);          // [64][4]           @8192  (1024 B)
    float* sCm = (float*)(sm + 9216);        // [8]               @9216
    __syncthreads();
    if (lt == 0) {
#pragma unroll
        for (int r = 0; r < 4; ++r) {
            const int row = wr * 32 + (r >> 1) * 16 + (r & 1) * 8 + lg;
#pragma unroll
            for (int j = 0; j < 4; ++j) {
                smV[(wc * 64 + row) * 4 + j] = v[r][j];
                smI[(wc * 64 + row) * 4 + j] = ix[r][j];
            }
        }
    }
    __syncthreads();
    if (wid < 2) {
        const int row = wid * 32 + lane;
        float fv[4]; int fi[4];
#pragma unroll
        for (int j = 0; j < 4; ++j) { fv[j] = 3.4e38f; fi[j] = 0x7fffffff; }
#pragma unroll
        for (int h = 0; h < 4; ++h)
#pragma unroll
            for (int j = 0; j < 4; ++j)
                ins4lex(smV[(h * 64 + row) * 4 + j], smI[(h * 64 + row) * 4 + j], fv, fi);
#pragma unroll
        for (int j = 0; j < 4; ++j) sFi[row * 4 + j] = fi[j];
    }
    __syncthreads();

    // ---------------- fused exact fp32 fixup + residual update ----------------
    float warp_commit = 0.0f;
    int* hist_q = g_hist + q * K_CODES;

#pragma unroll 1
    for (int i = 0; i < 8; ++i) {
        const int row = wid * 8 + i;
        const int m   = m0 + row;
        int cand[4];
#pragma unroll
        for (int c = 0; c < 4; ++c) cand[c] = sFi[row * 4 + c];

        const float4* xp = reinterpret_cast<const float4*>(g_X + (size_t)m * C_DIM);
        float4 xv[4];
#pragma unroll
        for (int j = 0; j < 4; ++j) xv[j] = xp[lane + 32 * j];

        float d[4];
#pragma unroll
        for (int c = 0; c < 4; ++c) {
            const float4* cp = reinterpret_cast<const float4*>(cbf + (size_t)cand[c] * C_DIM);
            float s = 0.0f;
#pragma unroll
            for (int j = 0; j < 4; ++j) {
                const float4 cv = cp[lane + 32 * j];
                const float dx = xv[j].x - cv.x, dy = xv[j].y - cv.y;
                const float dz = xv[j].z - cv.z, dw = xv[j].w - cv.w;
                s += dx * dx + dy * dy + dz * dz + dw * dw;
            }
            d[c] = s;
        }
#pragma unroll
        for (int c = 0; c < 4; ++c)
#pragma unroll
            for (int o = 16; o > 0; o >>= 1)
                d[c] += __shfl_xor_sync(0xffffffffu, d[c], o);

        float best = d[0]; int bi = cand[0];
#pragma unroll
        for (int c = 1; c < 4; ++c) {
            if (d[c] < best || (d[c] == best && cand[c] < bi)) {
                best = d[c]; bi = cand[c];
            }
        }

        const float4* bp = reinterpret_cast<const float4*>(cbf + (size_t)bi * C_DIM);
        float4* xo = reinterpret_cast<float4*>(g_X + (size_t)m * C_DIM);
        uint2*  xb = reinterpret_cast<uint2*>(g_Xb + (size_t)m * C_DIM);
#pragma unroll
        for (int j = 0; j < 4; ++j) {
            const float4 cv = bp[lane + 32 * j];
            float4 r;
            r.x = xv[j].x - cv.x; r.y = xv[j].y - cv.y;
            r.z = xv[j].z - cv.z; r.w = xv[j].w - cv.w;
            xo[lane + 32 * j] = r;
            __nv_bfloat162 h0 = {__float2bfloat16(r.x), __float2bfloat16(r.y)};
            __nv_bfloat162 h1 = {__float2bfloat16(r.z), __float2bfloat16(r.w)};
            uint2 pk;
            pk.x = *reinterpret_cast<uint32_t*>(&h0);
            pk.y = *reinterpret_cast<uint32_t*>(&h1);
            xb[lane + 32 * j] = pk;
        }

        if (lane == 0) {
            warp_commit += best;
            g_idx[q * M_TOT + m] = bi;
            atomicAdd(&hist_q[bi], 1);
        }
    }

    if (lane == 0) sCm[wid] = warp_commit;
    __syncthreads();
    if (tid == 0) {
        float cs = 0.0f;
#pragma unroll
        for (int w = 0; w < 8; ++w) cs += sCm[w];
        atomicAdd(&g_commit[q], (double)cs);
    }
}

// ---------------------------------------------------------------------------
// 4) Perplexity for all layers; re-zeroes histograms
// ---------------------------------------------------------------------------
__global__ void perp_all_kernel()
{
    __shared__ float red[1024];
    const int q = blockIdx.x;
    const int k = threadIdx.x;
    const float p = (float)g_hist[q * K_CODES + k] * (1.0f / (float)M_TOT);
    g_hist[q * K_CODES + k] = 0;
    red[k] = p * logf(p + 1e-7f);
    __syncthreads();
    for (int off = 512; off > 0; off >>= 1) {
        if (k < off) red[k] += red[k + off];
        __syncthreads();
    }
    if (k == 0) g_perp[q] = expf(-red[0]);
}

// ---------------------------------------------------------------------------
// 5) quantized_out: gather-sum 6 codes per (b,t), write transposed (B,C,T)
// ---------------------------------------------------------------------------
__global__ void qout_kernel(const float* __restrict__ codebooks,
                            float* __restrict__ out)
{
    __shared__ float tile[32][33];
    __shared__ int   sidx[Q_LAYERS][32];
    const int b  = blockIdx.z;
    const int c0 = blockIdx.y * 32;
    const int t0 = blockIdx.x * 32;
    const int tx = threadIdx.x;
    const int ty = threadIdx.y;
    const int tid = ty * 32 + tx;

    if (tid < Q_LAYERS * 32) {
        const int q = tid >> 5, t = tid & 31;
        sidx[q][t] = g_idx[q * M_TOT + b * T_DIM + t0 + t];
    }
    __syncthreads();

#pragma unroll
    for (int i = ty; i < 32; i += 8) {
        float s = 0.0f;
#pragma unroll
        for (int q = 0; q < Q_LAYERS; ++q)
            s += codebooks[((size_t)q * K_CODES + sidx[q][i]) * C_DIM + c0 + tx];
        tile[i][tx] = s;
    }
    __syncthreads();

    float* op = out + (size_t)b * C_DIM * T_DIM;
#pragma unroll
    for (int i = ty; i < 32; i += 8)
        op[(size_t)(c0 + i) * T_DIM + t0 + tx] = tile[tx][i];
}

// ---------------------------------------------------------------------------
// 6) Index output (B,T,Q) as float, and scalar losses
// ---------------------------------------------------------------------------
__global__ void idx_out_kernel(float* __restrict__ out)
{
    const int i = blockIdx.x * blockDim.x + threadIdx.x;
    if (i >= OUT_IDX_ELEMS) return;
    const int m = i / Q_LAYERS;
    const int q = i - m * Q_LAYERS;
    out[OUT_QOUT_ELEMS + i] = (float)g_idx[q * M_TOT + m];
}

__global__ void scalar_out_kernel(float* __restrict__ out)
{
    if (threadIdx.x == 0) {
        double cs = 0.0;
        float  ps = 0.0f;
        for (int q = 0; q < Q_LAYERS; ++q) {
            cs += g_commit[q] / (double)((double)M_TOT * (double)C_DIM);
            ps += g_perp[q];
        }
        out[OUT_QOUT_ELEMS + OUT_IDX_ELEMS + 0] = (float)(cs / (double)Q_LAYERS);
        out[OUT_QOUT_ELEMS + OUT_IDX_ELEMS + 1] = ps / (float)Q_LAYERS;
    }
}

// ---------------------------------------------------------------------------
extern "C" void kernel_launch(void* const* d_in, const int* in_sizes, int n_in,
                              void* d_out, int out_size)
{
    const float* x         = (const float*)d_in[0];
    const float* codebooks = (const float*)d_in[1];
    float* out = (float*)d_out;
    (void)in_sizes; (void)n_in; (void)out_size;

    static bool attr_set = false;
    if (!attr_set) {
        cudaFuncSetAttribute(gemm_fused_kernel,
                             cudaFuncAttributeMaxDynamicSharedMemorySize, SMEM_BYTES);
        attr_set = true;
    }

    transpose_in_kernel<<<dim3(T_DIM / 32, C_DIM / 32, B_DIM), dim3(32, 8)>>>(x);
    norms_all_kernel<<<Q_LAYERS * K_CODES, 128>>>(codebooks);

    for (int q = 0; q < Q_LAYERS; ++q) {
        const float* cb = codebooks + (size_t)q * K_CODES * C_DIM;
        gemm_fused_kernel<<<M_TOT / M_TILE, 256, SMEM_BYTES>>>(cb, q);
    }

    perp_all_kernel<<<Q_LAYERS, 1024>>>();
    qout_kernel<<<dim3(T_DIM / 32, C_DIM / 32, B_DIM), dim3(32, 8)>>>(codebooks, out);
    idx_out_kernel<<<(OUT_IDX_ELEMS + 255) / 256, 256>>>(out);
    scalar_out_kernel<<<1, 32>>>(out);
}

// round 8
// speedup vs baseline: 6.4746x; 1.0462x over previous
#include <cuda_runtime.h>
#include <cuda_bf16.h>
#include <cstdint>

// ---------------- problem constants ----------------
#define B_DIM    64
#define C_DIM    512
#define T_DIM    256
#define Q_LAYERS 6
#define K_CODES  1024
#define M_TOT    (B_DIM * T_DIM)                    // 16384
#define OUT_QOUT_ELEMS (B_DIM * C_DIM * T_DIM)      // 8388608
#define OUT_IDX_ELEMS  (B_DIM * T_DIM * Q_LAYERS)   // 98304

// ---------------- GEMM tiling (bf16) ----------------
#define M_TILE   64
#define N_TILE   256
#define N_PASSES (K_CODES / N_TILE)  // 4
#define KC       64                  // bf16 k-elems per staged chunk (128B/row)
#define K_CHUNKS (C_DIM / KC)        // 8 per pass
#define TOT_CHUNKS (N_PASSES * K_CHUNKS)  // 32 per layer
#define ROWB     144                 // 128B data + 16B pad (36-word stride: conflict-free)
#define A_BYTES  (M_TILE * ROWB)     // 9216
#define B_BYTES  (N_TILE * ROWB)     // 36864
#define STAGE_BYTES (A_BYTES + B_BYTES)      // 46080
#define MERGE_OFF   (2 * STAGE_BYTES)        // 92160
#define SMEM_BYTES  (MERGE_OFF + 9280)       // 101440 (2 CTAs/SM fits)

// ---------------- device scratch ----------------
__device__ __align__(16) float          g_X [M_TOT * C_DIM];
__device__ __align__(16) __nv_bfloat16  g_Xb[M_TOT * C_DIM];
__device__ __align__(16) __nv_bfloat16  g_CBb[Q_LAYERS * K_CODES * C_DIM];
__device__ int    g_idx[Q_LAYERS * M_TOT];
__device__ float  g_norm[Q_LAYERS * K_CODES];
__device__ int    g_hist[Q_LAYERS * K_CODES];
__device__ double g_commit[Q_LAYERS];
__device__ float  g_perp[Q_LAYERS];

// ---------------- helpers ----------------
__device__ __forceinline__ uint32_t smem_u32(const void* p) {
    uint32_t a;
    asm("{ .reg .u64 t; cvta.to.shared.u64 t, %1; cvt.u32.u64 %0, t; }" : "=r"(a) : "l"(p));
    return a;
}
__device__ __forceinline__ void cp_async16(uint32_t dst, const void* src) {
    asm volatile("cp.async.cg.shared.global [%0], [%1], 16;" :: "r"(dst), "l"(src));
}
__device__ __forceinline__ void cp_commit() {
    asm volatile("cp.async.commit_group;" ::: "memory");
}
template <int N> __device__ __forceinline__ void cp_wait() {
    asm volatile("cp.async.wait_group %0;" :: "n"(N) : "memory");
}
__device__ __forceinline__ void ldsm_x4(uint32_t& r0, uint32_t& r1,
                                        uint32_t& r2, uint32_t& r3, uint32_t addr) {
    asm volatile("ldmatrix.sync.aligned.m8n8.x4.shared.b16 {%0,%1,%2,%3}, [%4];"
                 : "=r"(r0), "=r"(r1), "=r"(r2), "=r"(r3) : "r"(addr));
}
__device__ __forceinline__ void mma_bf16(float* c, const uint32_t* a,
                                         uint32_t b0, uint32_t b1) {
    asm volatile(
        "mma.sync.aligned.m16n8k16.row.col.f32.bf16.bf16.f32 "
        "{%0,%1,%2,%3}, {%4,%5,%6,%7}, {%8,%9}, {%0,%1,%2,%3};"
        : "+f"(c[0]), "+f"(c[1]), "+f"(c[2]), "+f"(c[3])
        : "r"(a[0]), "r"(a[1]), "r"(a[2]), "r"(a[3]), "r"(b0), "r"(b1));
}

__device__ __forceinline__ void ins4(float s, int n, float v[4], int ix[4]) {
    if (s < v[3]) {
        if (s < v[1]) {
            if (s < v[0]) { v[3]=v[2];ix[3]=ix[2]; v[2]=v[1];ix[2]=ix[1];
                            v[1]=v[0];ix[1]=ix[0]; v[0]=s;ix[0]=n; }
            else          { v[3]=v[2];ix[3]=ix[2]; v[2]=v[1];ix[2]=ix[1];
                            v[1]=s;ix[1]=n; }
        } else {
            if (s < v[2]) { v[3]=v[2];ix[3]=ix[2]; v[2]=s;ix[2]=n; }
            else          { v[3]=s;ix[3]=n; }
        }
    }
}
__device__ __forceinline__ bool lexlt(float s, int n, float v, int i) {
    return (s < v) || (s == v && n < i);
}
__device__ __forceinline__ void ins4lex(float s, int n, float v[4], int ix[4]) {
    if (lexlt(s, n, v[3], ix[3])) {
        if (lexlt(s, n, v[1], ix[1])) {
            if (lexlt(s, n, v[0], ix[0])) { v[3]=v[2];ix[3]=ix[2]; v[2]=v[1];ix[2]=ix[1];
                                            v[1]=v[0];ix[1]=ix[0]; v[0]=s;ix[0]=n; }
            else                          { v[3]=v[2];ix[3]=ix[2]; v[2]=v[1];ix[2]=ix[1];
                                            v[1]=s;ix[1]=n; }
        } else {
            if (lexlt(s, n, v[2], ix[2])) { v[3]=v[2];ix[3]=ix[2]; v[2]=s;ix[2]=n; }
            else                          { v[3]=s;ix[3]=n; }
        }
    }
}

// ---------------------------------------------------------------------------
// 1) Transpose x (B,C,T) -> g_X fp32 + g_Xb bf16  (B*T, C)
// ---------------------------------------------------------------------------
__global__ void transpose_in_kernel(const float* __restrict__ x)
{
    __shared__ float tile[32][33];
    const int b  = blockIdx.z;
    const int c0 = blockIdx.y * 32;
    const int t0 = blockIdx.x * 32;
    const int tx = threadIdx.x;
    const int ty = threadIdx.y;

    const float* xp = x + (size_t)b * C_DIM * T_DIM;
#pragma unroll
    for (int i = ty; i < 32; i += 8)
        tile[i][tx] = xp[(size_t)(c0 + i) * T_DIM + t0 + tx];
    __syncthreads();
#pragma unroll
    for (int i = ty; i < 32; i += 8) {
        const float vv = tile[tx][i];
        const size_t o = (size_t)(b * T_DIM + t0 + i) * C_DIM + c0 + tx;
        g_X[o]  = vv;
        g_Xb[o] = __float2bfloat16(vv);
    }
}

// ---------------------------------------------------------------------------
// 2) Code norms + bf16 codebook conversion + zero commit accumulators
// ---------------------------------------------------------------------------
__global__ void norms_all_kernel(const float* __restrict__ codebooks)
{
    __shared__ float red[128];
    const int gk  = blockIdx.x;
    const int tid = threadIdx.x;
    const float4 c = reinterpret_cast<const float4*>(codebooks + (size_t)gk * C_DIM)[tid];
    red[tid] = c.x * c.x + c.y * c.y + c.z * c.z + c.w * c.w;

    __nv_bfloat162 h0 = {__float2bfloat16(c.x), __float2bfloat16(c.y)};
    __nv_bfloat162 h1 = {__float2bfloat16(c.z), __float2bfloat16(c.w)};
    __nv_bfloat162* dst = reinterpret_cast<__nv_bfloat162*>(g_CBb + (size_t)gk * C_DIM);
    dst[tid * 2]     = h0;
    dst[tid * 2 + 1] = h1;

    __syncthreads();
    for (int off = 64; off > 0; off >>= 1) {
        if (tid < off) red[tid] += red[tid + off];
        __syncthreads();
    }
    if (tid == 0) {
        g_norm[gk] = red[0];
        if (gk < Q_LAYERS) g_commit[gk] = 0.0;
    }
}

// ---------------------------------------------------------------------------
// 3) Persistent fused kernel: ALL 6 layers.
//    grid = 256 CTAs (64 private rows each), block = 256 thr, 2 CTAs/SM.
//    Per layer: flattened 32-chunk (KC=64) distance-1 cp.async pipeline,
//    bf16 mma + top-4, exact fp32 re-rank, residual update (fp32+bf16).
// ---------------------------------------------------------------------------
__device__ __forceinline__ void stage_chunk(uint32_t sbase, int buf, int cidx,
                                            int m0, const __nv_bfloat16* __restrict__ cbb,
                                            int tid)
{
    const int nt = cidx >> 3;
    const int kw = (cidx & 7) * KC;
    const uint32_t ab = sbase + (uint32_t)(buf * STAGE_BYTES);
    const uint32_t bb = ab + A_BYTES;
    // A: 64 rows x 8 x 16B = 512 units (2/thread)
#pragma unroll
    for (int i = 0; i < 2; ++i) {
        const int idx = tid + 256 * i;
        const int row = idx >> 3, g = idx & 7;
        cp_async16(ab + (uint32_t)(row * ROWB + g * 16),
                   g_Xb + (size_t)(m0 + row) * C_DIM + kw + g * 8);
    }
    // B: 256 rows x 8 x 16B = 2048 units (8/thread)
    const __nv_bfloat16* bsrc = cbb + (size_t)(nt * N_TILE) * C_DIM + kw;
#pragma unroll
    for (int i = 0; i < 8; ++i) {
        const int idx = tid + 256 * i;
        const int row = idx >> 3, g = idx & 7;
        cp_async16(bb + (uint32_t)(row * ROWB + g * 16),
                   bsrc + (size_t)row * C_DIM + g * 8);
    }
}

__global__ __launch_bounds__(256, 2) void rvq_fused_kernel(
    const float* __restrict__ cbf0)
{
    extern __shared__ char sm[];
    const uint32_t sbase = smem_u32(sm);

    const int tid  = threadIdx.x;
    const int wid  = tid >> 5;
    const int lane = tid & 31;
    const int wr   = wid & 1;        // row group (32 rows)
    const int wc   = wid >> 1;       // code group (64 codes within pass)
    const int lg   = lane >> 2;
    const int lt   = lane & 3;
    const int m0   = blockIdx.x * M_TILE;

    const uint32_t aoff0 = (uint32_t)((wr * 32 + (lane & 15)) * ROWB + (lane >> 4) * 16);
    const uint32_t aoff1 = aoff0 + 16 * ROWB;
    const uint32_t boff  = (uint32_t)((wc * 64 + (lane & 7) + ((lane >> 4) << 3)) * ROWB
                                      + (((lane >> 3) & 1) * 16));

    // merge scratch (beyond stage buffers)
    float* smV = (float*)(sm + MERGE_OFF);          // [4][64][4]
    int*   smI = (int*)(sm + MERGE_OFF + 4096);     // [4][64][4]
    int*   sFi = (int*)(sm + MERGE_OFF + 8192);     // [64][4]
    float* sCm = (float*)(sm + MERGE_OFF + 9216);   // [8]

    for (int q = 0; q < Q_LAYERS; ++q) {
        const __nv_bfloat16* __restrict__ cbb = g_CBb + (size_t)q * K_CODES * C_DIM;
        const float* __restrict__ cbf  = cbf0 + (size_t)q * K_CODES * C_DIM;
        const float* __restrict__ norms = g_norm + q * K_CODES;

        float v[4][4];
        int   ix[4][4];
#pragma unroll
        for (int r = 0; r < 4; ++r)
#pragma unroll
            for (int j = 0; j < 4; ++j) { v[r][j] = 3.4e38f; ix[r][j] = 0; }

        __syncthreads();                 // prev layer fixup done; buffers free
        stage_chunk(sbase, 0, 0, m0, cbb, tid); cp_commit();

        for (int nt = 0; nt < N_PASSES; ++nt) {
            float acc[2][8][4];
#pragma unroll
            for (int s = 0; s < 2; ++s)
#pragma unroll
                for (int ns = 0; ns < 8; ++ns)
#pragma unroll
                    for (int j = 0; j < 4; ++j) acc[s][ns][j] = 0.0f;

#pragma unroll 1
            for (int kc = 0; kc < K_CHUNKS; ++kc) {
                const int cidx = nt * K_CHUNKS + kc;
                cp_wait<0>();                   // chunk cidx resident
                __syncthreads();                // all warps done with buf (cidx+1)&1
                if (cidx + 1 < TOT_CHUNKS) {
                    stage_chunk(sbase, (cidx + 1) & 1, cidx + 1, m0, cbb, tid);
                    cp_commit();
                }

                const uint32_t Ab = sbase + (uint32_t)((cidx & 1) * STAGE_BYTES);
                const uint32_t Bb = Ab + A_BYTES;

#pragma unroll
                for (int ks = 0; ks < 4; ++ks) {
                    const uint32_t kb = (uint32_t)(ks * 32);
                    uint32_t a[2][4];
                    ldsm_x4(a[0][0], a[0][1], a[0][2], a[0][3], Ab + aoff0 + kb);
                    ldsm_x4(a[1][0], a[1][1], a[1][2], a[1][3], Ab + aoff1 + kb);
#pragma unroll
                    for (int p = 0; p < 4; ++p) {
                        uint32_t b0, b1, b2, b3;
                        ldsm_x4(b0, b1, b2, b3, Bb + boff + (uint32_t)(p * 16 * ROWB) + kb);
                        mma_bf16(acc[0][2 * p    ], a[0], b0, b1);
                        mma_bf16(acc[1][2 * p    ], a[1], b0, b1);
                        mma_bf16(acc[0][2 * p + 1], a[0], b2, b3);
                        mma_bf16(acc[1][2 * p + 1], a[1], b2, b3);
                    }
                }
            }

            // epilogue: score = ||cb||^2 - 2*dot; per-thread top-4
            const int nbase = nt * N_TILE + wc * 64 + lt * 2;
#pragma unroll
            for (int s = 0; s < 2; ++s) {
#pragma unroll
                for (int ns = 0; ns < 8; ++ns) {
                    const int n = nbase + ns * 8;
                    const float nm0 = __ldg(&norms[n]);
                    const float nm1 = __ldg(&norms[n + 1]);
                    ins4(fmaf(-2.0f, acc[s][ns][0], nm0), n,     v[s*2+0], ix[s*2+0]);
                    ins4(fmaf(-2.0f, acc[s][ns][1], nm1), n + 1, v[s*2+0], ix[s*2+0]);
                    ins4(fmaf(-2.0f, acc[s][ns][2], nm0), n,     v[s*2+1], ix[s*2+1]);
                    ins4(fmaf(-2.0f, acc[s][ns][3], nm1), n + 1, v[s*2+1], ix[s*2+1]);
                }
            }
        }

        // merge across lt (4 lanes per row)
#pragma unroll
        for (int r = 0; r < 4; ++r) {
#pragma unroll
            for (int o = 1; o <= 2; o <<= 1) {
                float ov[4]; int oi[4];
#pragma unroll
                for (int j = 0; j < 4; ++j) {
                    ov[j] = __shfl_xor_sync(0xffffffffu, v[r][j], o);
                    oi[j] = __shfl_xor_sync(0xffffffffu, ix[r][j], o);
                }
#pragma unroll
                for (int j = 0; j < 4; ++j) ins4lex(ov[j], oi[j], v[r], ix[r]);
            }
        }

        // cross-warp merge (4 wc groups) into sFi[64][4]
        __syncthreads();
        if (lt == 0) {
#pragma unroll
            for (int r = 0; r < 4; ++r) {
                const int row = wr * 32 + (r >> 1) * 16 + (r & 1) * 8 + lg;
#pragma unroll
                for (int j = 0; j < 4; ++j) {
                    smV[(wc * 64 + row) * 4 + j] = v[r][j];
                    smI[(wc * 64 + row) * 4 + j] = ix[r][j];
                }
            }
        }
        __syncthreads();
        if (wid < 2) {
            const int row = wid * 32 + lane;
            float fv[4]; int fi[4];
#pragma unroll
            for (int j = 0; j < 4; ++j) { fv[j] = 3.4e38f; fi[j] = 0x7fffffff; }
#pragma unroll
            for (int h = 0; h < 4; ++h)
#pragma unroll
                for (int j = 0; j < 4; ++j)
                    ins4lex(smV[(h * 64 + row) * 4 + j], smI[(h * 64 + row) * 4 + j], fv, fi);
#pragma unroll
            for (int j = 0; j < 4; ++j) sFi[row * 4 + j] = fi[j];
        }
        __syncthreads();

        // ---------------- exact fp32 fixup + residual update ----------------
        float warp_commit = 0.0f;
        int* hist_q = g_hist + q * K_CODES;

#pragma unroll 1
        for (int i = 0; i < 8; ++i) {
            const int row = wid * 8 + i;
            const int m   = m0 + row;
            int cand[4];
#pragma unroll
            for (int c = 0; c < 4; ++c) cand[c] = sFi[row * 4 + c];

            const float4* xp = reinterpret_cast<const float4*>(g_X + (size_t)m * C_DIM);
            float4 xv[4];
#pragma unroll
            for (int j = 0; j < 4; ++j) xv[j] = xp[lane + 32 * j];

            float d[4];
#pragma unroll
            for (int c = 0; c < 4; ++c) {
                const float4* cp = reinterpret_cast<const float4*>(cbf + (size_t)cand[c] * C_DIM);
                float s = 0.0f;
#pragma unroll
                for (int j = 0; j < 4; ++j) {
                    const float4 cv = cp[lane + 32 * j];
                    const float dx = xv[j].x - cv.x, dy = xv[j].y - cv.y;
                    const float dz = xv[j].z - cv.z, dw = xv[j].w - cv.w;
                    s += dx * dx + dy * dy + dz * dz + dw * dw;
                }
                d[c] = s;
            }
#pragma unroll
            for (int c = 0; c < 4; ++c)
#pragma unroll
                for (int o = 16; o > 0; o >>= 1)
                    d[c] += __shfl_xor_sync(0xffffffffu, d[c], o);

            float best = d[0]; int bi = cand[0];
#pragma unroll
            for (int c = 1; c < 4; ++c) {
                if (d[c] < best || (d[c] == best && cand[c] < bi)) {
                    best = d[c]; bi = cand[c];
                }
            }

            const float4* bp = reinterpret_cast<const float4*>(cbf + (size_t)bi * C_DIM);
            float4* xo = reinterpret_cast<float4*>(g_X + (size_t)m * C_DIM);
            uint2*  xb = reinterpret_cast<uint2*>(g_Xb + (size_t)m * C_DIM);
#pragma unroll
            for (int j = 0; j < 4; ++j) {
                const float4 cv = bp[lane + 32 * j];
                float4 r;
                r.x = xv[j].x - cv.x; r.y = xv[j].y - cv.y;
                r.z = xv[j].z - cv.z; r.w = xv[j].w - cv.w;
                xo[lane + 32 * j] = r;
                __nv_bfloat162 h0 = {__float2bfloat16(r.x), __float2bfloat16(r.y)};
                __nv_bfloat162 h1 = {__float2bfloat16(r.z), __float2bfloat16(r.w)};
                uint2 pk;
                pk.x = *reinterpret_cast<uint32_t*>(&h0);
                pk.y = *reinterpret_cast<uint32_t*>(&h1);
                xb[lane + 32 * j] = pk;
            }

            if (lane == 0) {
                warp_commit += best;
                g_idx[q * M_TOT + m] = bi;
                atomicAdd(&hist_q[bi], 1);
            }
        }

        if (lane == 0) sCm[wid] = warp_commit;
        __threadfence_block();           // g_Xb writes visible before next layer A staging
        __syncthreads();
        if (tid == 0) {
            float cs = 0.0f;
#pragma unroll
            for (int w = 0; w < 8; ++w) cs += sCm[w];
            atomicAdd(&g_commit[q], (double)cs);
        }
    }
}

// ---------------------------------------------------------------------------
// 4) Perplexity for all layers; re-zeroes histograms
// ---------------------------------------------------------------------------
__global__ void perp_all_kernel()
{
    __shared__ float red[1024];
    const int q = blockIdx.x;
    const int k = threadIdx.x;
    const float p = (float)g_hist[q * K_CODES + k] * (1.0f / (float)M_TOT);
    g_hist[q * K_CODES + k] = 0;
    red[k] = p * logf(p + 1e-7f);
    __syncthreads();
    for (int off = 512; off > 0; off >>= 1) {
        if (k < off) red[k] += red[k + off];
        __syncthreads();
    }
    if (k == 0) g_perp[q] = expf(-red[0]);
}

// ---------------------------------------------------------------------------
// 5) quantized_out: gather-sum 6 codes per (b,t), write transposed (B,C,T)
// ---------------------------------------------------------------------------
__global__ void qout_kernel(const float* __restrict__ codebooks,
                            float* __restrict__ out)
{
    __shared__ float tile[32][33];
    __shared__ int   sidx[Q_LAYERS][32];
    const int b  = blockIdx.z;
    const int c0 = blockIdx.y * 32;
    const int t0 = blockIdx.x * 32;
    const int tx = threadIdx.x;
    const int ty = threadIdx.y;
    const int tid = ty * 32 + tx;

    if (tid < Q_LAYERS * 32) {
        const int q = tid >> 5, t = tid & 31;
        sidx[q][t] = g_idx[q * M_TOT + b * T_DIM + t0 + t];
    }
    __syncthreads();

#pragma unroll
    for (int i = ty; i < 32; i += 8) {
        float s = 0.0f;
#pragma unroll
        for (int q = 0; q < Q_LAYERS; ++q)
            s += codebooks[((size_t)q * K_CODES + sidx[q][i]) * C_DIM + c0 + tx];
        tile[i][tx] = s;
    }
    __syncthreads();

    float* op = out + (size_t)b * C_DIM * T_DIM;
#pragma unroll
    for (int i = ty; i < 32; i += 8)
        op[(size_t)(c0 + i) * T_DIM + t0 + tx] = tile[tx][i];
}

// ---------------------------------------------------------------------------
// 6) Index output (B,T,Q) as float, and scalar losses
// ---------------------------------------------------------------------------
__global__ void idx_out_kernel(float* __restrict__ out)
{
    const int i = blockIdx.x * blockDim.x + threadIdx.x;
    if (i >= OUT_IDX_ELEMS) return;
    const int m = i / Q_LAYERS;
    const int q = i - m * Q_LAYERS;
    out[OUT_QOUT_ELEMS + i] = (float)g_idx[q * M_TOT + m];
}

__global__ void scalar_out_kernel(float* __restrict__ out)
{
    if (threadIdx.x == 0) {
        double cs = 0.0;
        float  ps = 0.0f;
        for (int q = 0; q < Q_LAYERS; ++q) {
            cs += g_commit[q] / (double)((double)M_TOT * (double)C_DIM);
            ps += g_perp[q];
        }
        out[OUT_QOUT_ELEMS + OUT_IDX_ELEMS + 0] = (float)(cs / (double)Q_LAYERS);
        out[OUT_QOUT_ELEMS + OUT_IDX_ELEMS + 1] = ps / (float)Q_LAYERS;
    }
}

// ---------------------------------------------------------------------------
extern "C" void kernel_launch(void* const* d_in, const int* in_sizes, int n_in,
                              void* d_out, int out_size)
{
    const float* x         = (const float*)d_in[0];
    const float* codebooks = (const float*)d_in[1];
    float* out = (float*)d_out;
    (void)in_sizes; (void)n_in; (void)out_size;

    static bool attr_set = false;
    if (!attr_set) {
        cudaFuncSetAttribute(rvq_fused_kernel,
                             cudaFuncAttributeMaxDynamicSharedMemorySize, SMEM_BYTES);
        attr_set = true;
    }

    transpose_in_kernel<<<dim3(T_DIM / 32, C_DIM / 32, B_DIM), dim3(32, 8)>>>(x);
    norms_all_kernel<<<Q_LAYERS * K_CODES, 128>>>(codebooks);

    rvq_fused_kernel<<<M_TOT / M_TILE, 256, SMEM_BYTES>>>(codebooks);

    perp_all_kernel<<<Q_LAYERS, 1024>>>();
    qout_kernel<<<dim3(T_DIM / 32, C_DIM / 32, B_DIM), dim3(32, 8)>>>(codebooks, out);
    idx_out_kernel<<<(OUT_IDX_ELEMS + 255) / 256, 256>>>(out);
    scalar_out_kernel<<<1, 32>>>(out);
}

// round 9
// speedup vs baseline: 6.6810x; 1.0319x over previous
#include <cuda_runtime.h>
#include <cuda_bf16.h>
#include <cstdint>

// ---------------- problem constants ----------------
#define B_DIM    64
#define C_DIM    512
#define T_DIM    256
#define Q_LAYERS 6
#define K_CODES  1024
#define M_TOT    (B_DIM * T_DIM)                    // 16384
#define OUT_QOUT_ELEMS (B_DIM * C_DIM * T_DIM)      // 8388608
#define OUT_IDX_ELEMS  (B_DIM * T_DIM * Q_LAYERS)   // 98304

// ---------------- GEMM tiling (bf16) ----------------
#define M_TILE   64
#define N_TILE   256
#define N_PASSES (K_CODES / N_TILE)  // 4
#define KC       64                  // bf16 k-elems per staged chunk (128B/row)
#define K_CHUNKS (C_DIM / KC)        // 8 per pass
#define TOT_CHUNKS (N_PASSES * K_CHUNKS)  // 32 per layer
#define ROWB     144                 // 128B data + 16B pad (conflict-free ldmatrix)
#define A_BYTES  (M_TILE * ROWB)     // 9216
#define B_BYTES  (N_TILE * ROWB)     // 36864
#define STAGE_BYTES (A_BYTES + B_BYTES)      // 46080
#define MERGE_OFF   (2 * STAGE_BYTES)        // 92160
#define SMEM_BYTES  (MERGE_OFF + 9280)       // 101440 (2 CTAs/SM)

// ---------------- device scratch ----------------
__device__ __align__(16) float          g_X [M_TOT * C_DIM];
__device__ __align__(16) __nv_bfloat16  g_Xb[M_TOT * C_DIM];
__device__ __align__(16) __nv_bfloat16  g_CBb[Q_LAYERS * K_CODES * C_DIM];
__device__ int    g_idx[Q_LAYERS * M_TOT];
__device__ float  g_norm[Q_LAYERS * K_CODES];
__device__ int    g_hist[Q_LAYERS * K_CODES];
__device__ double g_commit[Q_LAYERS];
__device__ float  g_perp[Q_LAYERS];

// ---------------- helpers ----------------
__device__ __forceinline__ uint32_t smem_u32(const void* p) {
    uint32_t a;
    asm("{ .reg .u64 t; cvta.to.shared.u64 t, %1; cvt.u32.u64 %0, t; }" : "=r"(a) : "l"(p));
    return a;
}
__device__ __forceinline__ void cp_async16(uint32_t dst, const void* src) {
    asm volatile("cp.async.cg.shared.global [%0], [%1], 16;" :: "r"(dst), "l"(src));
}
__device__ __forceinline__ void cp_commit() {
    asm volatile("cp.async.commit_group;" ::: "memory");
}
template <int N> __device__ __forceinline__ void cp_wait() {
    asm volatile("cp.async.wait_group %0;" :: "n"(N) : "memory");
}
__device__ __forceinline__ void ldsm_x4(uint32_t& r0, uint32_t& r1,
                                        uint32_t& r2, uint32_t& r3, uint32_t addr) {
    asm volatile("ldmatrix.sync.aligned.m8n8.x4.shared.b16 {%0,%1,%2,%3}, [%4];"
                 : "=r"(r0), "=r"(r1), "=r"(r2), "=r"(r3) : "r"(addr));
}
__device__ __forceinline__ void mma_bf16(float* c, const uint32_t* a,
                                         uint32_t b0, uint32_t b1) {
    asm volatile(
        "mma.sync.aligned.m16n8k16.row.col.f32.bf16.bf16.f32 "
        "{%0,%1,%2,%3}, {%4,%5,%6,%7}, {%8,%9}, {%0,%1,%2,%3};"
        : "+f"(c[0]), "+f"(c[1]), "+f"(c[2]), "+f"(c[3])
        : "r"(a[0]), "r"(a[1]), "r"(a[2]), "r"(a[3]), "r"(b0), "r"(b1));
}

__device__ __forceinline__ void ins4(float s, int n, float v[4], int ix[4]) {
    if (s < v[3]) {
        if (s < v[1]) {
            if (s < v[0]) { v[3]=v[2];ix[3]=ix[2]; v[2]=v[1];ix[2]=ix[1];
                            v[1]=v[0];ix[1]=ix[0]; v[0]=s;ix[0]=n; }
            else          { v[3]=v[2];ix[3]=ix[2]; v[2]=v[1];ix[2]=ix[1];
                            v[1]=s;ix[1]=n; }
        } else {
            if (s < v[2]) { v[3]=v[2];ix[3]=ix[2]; v[2]=s;ix[2]=n; }
            else          { v[3]=s;ix[3]=n; }
        }
    }
}
__device__ __forceinline__ bool lexlt(float s, int n, float v, int i) {
    return (s < v) || (s == v && n < i);
}
__device__ __forceinline__ void ins4lex(float s, int n, float v[4], int ix[4]) {
    if (lexlt(s, n, v[3], ix[3])) {
        if (lexlt(s, n, v[1], ix[1])) {
            if (lexlt(s, n, v[0], ix[0])) { v[3]=v[2];ix[3]=ix[2]; v[2]=v[1];ix[2]=ix[1];
                                            v[1]=v[0];ix[1]=ix[0]; v[0]=s;ix[0]=n; }
            else                          { v[3]=v[2];ix[3]=ix[2]; v[2]=v[1];ix[2]=ix[1];
                                            v[1]=s;ix[1]=n; }
        } else {
            if (lexlt(s, n, v[2], ix[2])) { v[3]=v[2];ix[3]=ix[2]; v[2]=s;ix[2]=n; }
            else                          { v[3]=s;ix[3]=n; }
        }
    }
}

// ---------------------------------------------------------------------------
// 1) prep: transpose x -> g_X/g_Xb  AND  norms + bf16 codebook (one kernel)
//    grid = 8192 (transpose) + 6144 (norms) blocks, 256 threads.
// ---------------------------------------------------------------------------
#define PREP_TR_BLOCKS 8192
#define PREP_BLOCKS    (PREP_TR_BLOCKS + Q_LAYERS * K_CODES)

__global__ __launch_bounds__(256) void prep_kernel(
    const float* __restrict__ x, const float* __restrict__ codebooks)
{
    __shared__ float sred[32 * 33];   // transpose tile / norms reduction
    const int bid = blockIdx.x;
    const int tid = threadIdx.x;

    if (bid < PREP_TR_BLOCKS) {
        // transpose block
        const int b  = bid >> 7;
        const int r  = bid & 127;
        const int c0 = (r >> 3) * 32;
        const int t0 = (r & 7) * 32;
        const int tx = tid & 31;
        const int ty = tid >> 5;      // 0..7
        float (*tile)[33] = reinterpret_cast<float(*)[33]>(sred);

        const float* xp = x + (size_t)b * C_DIM * T_DIM;
#pragma unroll
        for (int i = ty; i < 32; i += 8)
            tile[i][tx] = xp[(size_t)(c0 + i) * T_DIM + t0 + tx];
        __syncthreads();
#pragma unroll
        for (int i = ty; i < 32; i += 8) {
            const float vv = tile[tx][i];
            const size_t o = (size_t)(b * T_DIM + t0 + i) * C_DIM + c0 + tx;
            g_X[o]  = vv;
            g_Xb[o] = __float2bfloat16(vv);
        }
    } else {
        // norms + bf16 conversion for codebook row gk
        const int gk = bid - PREP_TR_BLOCKS;            // 0 .. 6143
        const float2 c = reinterpret_cast<const float2*>(codebooks + (size_t)gk * C_DIM)[tid];
        sred[tid] = c.x * c.x + c.y * c.y;
        __nv_bfloat162 h = {__float2bfloat16(c.x), __float2bfloat16(c.y)};
        reinterpret_cast<__nv_bfloat162*>(g_CBb + (size_t)gk * C_DIM)[tid] = h;
        __syncthreads();
        for (int off = 128; off > 0; off >>= 1) {
            if (tid < off) sred[tid] += sred[tid + off];
            __syncthreads();
        }
        if (tid == 0) {
            g_norm[gk] = sred[0];
            if (gk < Q_LAYERS) g_commit[gk] = 0.0;
        }
    }
}

// ---------------------------------------------------------------------------
// 2) Persistent fused kernel: all 6 layers (as round 8) + cross-layer prestage
// ---------------------------------------------------------------------------
__device__ __forceinline__ void stage_A_chunk(uint32_t sbase, int buf, int cidx,
                                              int m0, int tid)
{
    const int kw = (cidx & 7) * KC;
    const uint32_t ab = sbase + (uint32_t)(buf * STAGE_BYTES);
#pragma unroll
    for (int i = 0; i < 2; ++i) {
        const int idx = tid + 256 * i;
        const int row = idx >> 3, g = idx & 7;
        cp_async16(ab + (uint32_t)(row * ROWB + g * 16),
                   g_Xb + (size_t)(m0 + row) * C_DIM + kw + g * 8);
    }
}
__device__ __forceinline__ void stage_B_chunk(uint32_t sbase, int buf, int cidx,
                                              const __nv_bfloat16* __restrict__ cbb,
                                              int tid)
{
    const int nt = cidx >> 3;
    const int kw = (cidx & 7) * KC;
    const uint32_t bb = sbase + (uint32_t)(buf * STAGE_BYTES) + A_BYTES;
    const __nv_bfloat16* bsrc = cbb + (size_t)(nt * N_TILE) * C_DIM + kw;
#pragma unroll
    for (int i = 0; i < 8; ++i) {
        const int idx = tid + 256 * i;
        const int row = idx >> 3, g = idx & 7;
        cp_async16(bb + (uint32_t)(row * ROWB + g * 16),
                   bsrc + (size_t)row * C_DIM + g * 8);
    }
}

__global__ __launch_bounds__(256, 2) void rvq_fused_kernel(
    const float* __restrict__ cbf0)
{
    extern __shared__ char sm[];
    const uint32_t sbase = smem_u32(sm);

    const int tid  = threadIdx.x;
    const int wid  = tid >> 5;
    const int lane = tid & 31;
    const int wr   = wid & 1;
    const int wc   = wid >> 1;
    const int lg   = lane >> 2;
    const int lt   = lane & 3;
    const int m0   = blockIdx.x * M_TILE;

    const uint32_t aoff0 = (uint32_t)((wr * 32 + (lane & 15)) * ROWB + (lane >> 4) * 16);
    const uint32_t aoff1 = aoff0 + 16 * ROWB;
    const uint32_t boff  = (uint32_t)((wc * 64 + (lane & 7) + ((lane >> 4) << 3)) * ROWB
                                      + (((lane >> 3) & 1) * 16));

    float* smV = (float*)(sm + MERGE_OFF);          // [4][64][4]
    int*   smI = (int*)(sm + MERGE_OFF + 4096);     // [4][64][4]
    int*   sFi = (int*)(sm + MERGE_OFF + 8192);     // [64][4]
    float* sCm = (float*)(sm + MERGE_OFF + 9216);   // [8]

    for (int q = 0; q < Q_LAYERS; ++q) {
        const __nv_bfloat16* __restrict__ cbb = g_CBb + (size_t)q * K_CODES * C_DIM;
        const float* __restrict__ cbf  = cbf0 + (size_t)q * K_CODES * C_DIM;
        const float* __restrict__ norms = g_norm + q * K_CODES;

        float v[4][4];
        int   ix[4][4];
#pragma unroll
        for (int r = 0; r < 4; ++r)
#pragma unroll
            for (int j = 0; j < 4; ++j) { v[r][j] = 3.4e38f; ix[r][j] = 0; }

        if (q == 0) {
            __syncthreads();
            stage_A_chunk(sbase, 0, 0, m0, tid);
            stage_B_chunk(sbase, 0, 0, cbb, tid);
            cp_commit();
        }
        // q > 0: chunk 0 already prestaged across the layer boundary

        for (int nt = 0; nt < N_PASSES; ++nt) {
            float acc[2][8][4];
#pragma unroll
            for (int s = 0; s < 2; ++s)
#pragma unroll
                for (int ns = 0; ns < 8; ++ns)
#pragma unroll
                    for (int j = 0; j < 4; ++j) acc[s][ns][j] = 0.0f;

#pragma unroll 1
            for (int kc = 0; kc < K_CHUNKS; ++kc) {
                const int cidx = nt * K_CHUNKS + kc;
                cp_wait<0>();
                __syncthreads();
                if (cidx + 1 < TOT_CHUNKS) {
                    stage_A_chunk(sbase, (cidx + 1) & 1, cidx + 1, m0, tid);
                    stage_B_chunk(sbase, (cidx + 1) & 1, cidx + 1, cbb, tid);
                    cp_commit();
                }

                const uint32_t Ab = sbase + (uint32_t)((cidx & 1) * STAGE_BYTES);
                const uint32_t Bb = Ab + A_BYTES;

#pragma unroll
                for (int ks = 0; ks < 4; ++ks) {
                    const uint32_t kb = (uint32_t)(ks * 32);
                    uint32_t a[2][4];
                    ldsm_x4(a[0][0], a[0][1], a[0][2], a[0][3], Ab + aoff0 + kb);
                    ldsm_x4(a[1][0], a[1][1], a[1][2], a[1][3], Ab + aoff1 + kb);
#pragma unroll
                    for (int p = 0; p < 4; ++p) {
                        uint32_t b0, b1, b2, b3;
                        ldsm_x4(b0, b1, b2, b3, Bb + boff + (uint32_t)(p * 16 * ROWB) + kb);
                        mma_bf16(acc[0][2 * p    ], a[0], b0, b1);
                        mma_bf16(acc[1][2 * p    ], a[1], b0, b1);
                        mma_bf16(acc[0][2 * p + 1], a[0], b2, b3);
                        mma_bf16(acc[1][2 * p + 1], a[1], b2, b3);
                    }
                }
            }

            // epilogue: score = ||cb||^2 - 2*dot
            const int nbase = nt * N_TILE + wc * 64 + lt * 2;
#pragma unroll
            for (int s = 0; s < 2; ++s) {
#pragma unroll
                for (int ns = 0; ns < 8; ++ns) {
                    const int n = nbase + ns * 8;
                    const float nm0 = __ldg(&norms[n]);
                    const float nm1 = __ldg(&norms[n + 1]);
                    ins4(fmaf(-2.0f, acc[s][ns][0], nm0), n,     v[s*2+0], ix[s*2+0]);
                    ins4(fmaf(-2.0f, acc[s][ns][1], nm1), n + 1, v[s*2+0], ix[s*2+0]);
                    ins4(fmaf(-2.0f, acc[s][ns][2], nm0), n,     v[s*2+1], ix[s*2+1]);
                    ins4(fmaf(-2.0f, acc[s][ns][3], nm1), n + 1, v[s*2+1], ix[s*2+1]);
                }
            }
        }

        // merge across lt lanes
#pragma unroll
        for (int r = 0; r < 4; ++r) {
#pragma unroll
            for (int o = 1; o <= 2; o <<= 1) {
                float ov[4]; int oi[4];
#pragma unroll
                for (int j = 0; j < 4; ++j) {
                    ov[j] = __shfl_xor_sync(0xffffffffu, v[r][j], o);
                    oi[j] = __shfl_xor_sync(0xffffffffu, ix[r][j], o);
                }
#pragma unroll
                for (int j = 0; j < 4; ++j) ins4lex(ov[j], oi[j], v[r], ix[r]);
            }
        }

        // cross-warp merge into sFi[64][4]
        __syncthreads();
        if (lt == 0) {
#pragma unroll
            for (int r = 0; r < 4; ++r) {
                const int row = wr * 32 + (r >> 1) * 16 + (r & 1) * 8 + lg;
#pragma unroll
                for (int j = 0; j < 4; ++j) {
                    smV[(wc * 64 + row) * 4 + j] = v[r][j];
                    smI[(wc * 64 + row) * 4 + j] = ix[r][j];
                }
            }
        }
        __syncthreads();
        if (wid < 2) {
            const int row = wid * 32 + lane;
            float fv[4]; int fi[4];
#pragma unroll
            for (int j = 0; j < 4; ++j) { fv[j] = 3.4e38f; fi[j] = 0x7fffffff; }
#pragma unroll
            for (int h = 0; h < 4; ++h)
#pragma unroll
                for (int j = 0; j < 4; ++j)
                    ins4lex(smV[(h * 64 + row) * 4 + j], smI[(h * 64 + row) * 4 + j], fv, fi);
#pragma unroll
            for (int j = 0; j < 4; ++j) sFi[row * 4 + j] = fi[j];
        }
        __syncthreads();

        // prestage next layer's B (codebook — independent of fixup) into buf0
        if (q + 1 < Q_LAYERS) {
            stage_B_chunk(sbase, 0, 0, g_CBb + (size_t)(q + 1) * K_CODES * C_DIM, tid);
            cp_commit();
        }

        // ---------------- exact fp32 fixup + residual update ----------------
        float warp_commit = 0.0f;
        int* hist_q = g_hist + q * K_CODES;

#pragma unroll 1
        for (int i = 0; i < 8; ++i) {
            const int row = wid * 8 + i;
            const int m   = m0 + row;
            int cand[4];
#pragma unroll
            for (int c = 0; c < 4; ++c) cand[c] = sFi[row * 4 + c];

            const float4* xp = reinterpret_cast<const float4*>(g_X + (size_t)m * C_DIM);
            float4 xv[4];
#pragma unroll
            for (int j = 0; j < 4; ++j) xv[j] = xp[lane + 32 * j];

            float d[4];
#pragma unroll
            for (int c = 0; c < 4; ++c) {
                const float4* cp = reinterpret_cast<const float4*>(cbf + (size_t)cand[c] * C_DIM);
                float s = 0.0f;
#pragma unroll
                for (int j = 0; j < 4; ++j) {
                    const float4 cv = cp[lane + 32 * j];
                    const float dx = xv[j].x - cv.x, dy = xv[j].y - cv.y;
                    const float dz = xv[j].z - cv.z, dw = xv[j].w - cv.w;
                    s += dx * dx + dy * dy + dz * dz + dw * dw;
                }
                d[c] = s;
            }
#pragma unroll
            for (int c = 0; c < 4; ++c)
#pragma unroll
                for (int o = 16; o > 0; o >>= 1)
                    d[c] += __shfl_xor_sync(0xffffffffu, d[c], o);

            float best = d[0]; int bi = cand[0];
#pragma unroll
            for (int c = 1; c < 4; ++c) {
                if (d[c] < best || (d[c] == best && cand[c] < bi)) {
                    best = d[c]; bi = cand[c];
                }
            }

            const float4* bp = reinterpret_cast<const float4*>(cbf + (size_t)bi * C_DIM);
            float4* xo = reinterpret_cast<float4*>(g_X + (size_t)m * C_DIM);
            uint2*  xb = reinterpret_cast<uint2*>(g_Xb + (size_t)m * C_DIM);
#pragma unroll
            for (int j = 0; j < 4; ++j) {
                const float4 cv = bp[lane + 32 * j];
                float4 r;
                r.x = xv[j].x - cv.x; r.y = xv[j].y - cv.y;
                r.z = xv[j].z - cv.z; r.w = xv[j].w - cv.w;
                xo[lane + 32 * j] = r;
                __nv_bfloat162 h0 = {__float2bfloat16(r.x), __float2bfloat16(r.y)};
                __nv_bfloat162 h1 = {__float2bfloat16(r.z), __float2bfloat16(r.w)};
                uint2 pk;
                pk.x = *reinterpret_cast<uint32_t*>(&h0);
                pk.y = *reinterpret_cast<uint32_t*>(&h1);
                xb[lane + 32 * j] = pk;
            }

            if (lane == 0) {
                warp_commit += best;
                g_idx[q * M_TOT + m] = bi;
                atomicAdd(&hist_q[bi], 1);
            }
        }

        if (lane == 0) sCm[wid] = warp_commit;
        __threadfence_block();           // residual writes visible before A staging
        __syncthreads();
        if (tid == 0) {
            float cs = 0.0f;
#pragma unroll
            for (int w = 0; w < 8; ++w) cs += sCm[w];
            atomicAdd(&g_commit[q], (double)cs);
        }

        // prestage next layer's A (depends on the fixup just completed)
        if (q + 1 < Q_LAYERS) {
            stage_A_chunk(sbase, 0, 0, m0, tid);
            cp_commit();
        }
    }
}

// ---------------------------------------------------------------------------
// 3) Perplexity for all layers; re-zeroes histograms
// ---------------------------------------------------------------------------
__global__ void perp_all_kernel()
{
    __shared__ float red[1024];
    const int q = blockIdx.x;
    const int k = threadIdx.x;
    const float p = (float)g_hist[q * K_CODES + k] * (1.0f / (float)M_TOT);
    g_hist[q * K_CODES + k] = 0;
    red[k] = p * logf(p + 1e-7f);
    __syncthreads();
    for (int off = 512; off > 0; off >>= 1) {
        if (k < off) red[k] += red[k + off];
        __syncthreads();
    }
    if (k == 0) g_perp[q] = expf(-red[0]);
}

// ---------------------------------------------------------------------------
// 4) finish: qout (8192 blocks) + idx out (384 blocks) + scalars (1 block)
// ---------------------------------------------------------------------------
#define FIN_QOUT_BLOCKS 8192
#define FIN_IDX_BLOCKS  (OUT_IDX_ELEMS / 256)       // 384
#define FIN_BLOCKS      (FIN_QOUT_BLOCKS + FIN_IDX_BLOCKS + 1)

__global__ __launch_bounds__(256) void finish_kernel(
    const float* __restrict__ codebooks, float* __restrict__ out)
{
    const int bid = blockIdx.x;
    const int tid = threadIdx.x;

    if (bid < FIN_QOUT_BLOCKS) {
        __shared__ float tile[32][33];
        __shared__ int   sidx[Q_LAYERS][32];
        const int b  = bid >> 7;
        const int r  = bid & 127;
        const int c0 = (r >> 3) * 32;
        const int t0 = (r & 7) * 32;
        const int tx = tid & 31;
        const int ty = tid >> 5;

        if (tid < Q_LAYERS * 32) {
            const int q = tid >> 5, t = tid & 31;
            sidx[q][t] = g_idx[q * M_TOT + b * T_DIM + t0 + t];
        }
        __syncthreads();

#pragma unroll
        for (int i = ty; i < 32; i += 8) {
            float s = 0.0f;
#pragma unroll
            for (int q = 0; q < Q_LAYERS; ++q)
                s += codebooks[((size_t)q * K_CODES + sidx[q][i]) * C_DIM + c0 + tx];
            tile[i][tx] = s;
        }
        __syncthreads();

        float* op = out + (size_t)b * C_DIM * T_DIM;
#pragma unroll
        for (int i = ty; i < 32; i += 8)
            op[(size_t)(c0 + i) * T_DIM + t0 + tx] = tile[tx][i];
    } else if (bid < FIN_QOUT_BLOCKS + FIN_IDX_BLOCKS) {
        const int i = (bid - FIN_QOUT_BLOCKS) * 256 + tid;
        const int m = i / Q_LAYERS;
        const int q = i - m * Q_LAYERS;
        out[OUT_QOUT_ELEMS + i] = (float)g_idx[q * M_TOT + m];
    } else {
        if (tid == 0) {
            double cs = 0.0;
            float  ps = 0.0f;
            for (int q = 0; q < Q_LAYERS; ++q) {
                cs += g_commit[q] / (double)((double)M_TOT * (double)C_DIM);
                ps += g_perp[q];
            }
            out[OUT_QOUT_ELEMS + OUT_IDX_ELEMS + 0] = (float)(cs / (double)Q_LAYERS);
            out[OUT_QOUT_ELEMS + OUT_IDX_ELEMS + 1] = ps / (float)Q_LAYERS;
        }
    }
}

// ---------------------------------------------------------------------------
extern "C" void kernel_launch(void* const* d_in, const int* in_sizes, int n_in,
                              void* d_out, int out_size)
{
    const float* x         = (const float*)d_in[0];
    const float* codebooks = (const float*)d_in[1];
    float* out = (float*)d_out;
    (void)in_sizes; (void)n_in; (void)out_size;

    static bool attr_set = false;
    if (!attr_set) {
        cudaFuncSetAttribute(rvq_fused_kernel,
                             cudaFuncAttributeMaxDynamicSharedMemorySize, SMEM_BYTES);
        attr_set = true;
    }

    prep_kernel<<<PREP_BLOCKS, 256>>>(x, codebooks);
    rvq_fused_kernel<<<M_TOT / M_TILE, 256, SMEM_BYTES>>>(codebooks);
    perp_all_kernel<<<Q_LAYERS, 1024>>>();
    finish_kernel<<<FIN_BLOCKS, 256>>>(codebooks, out);
}